// round 7
// baseline (speedup 1.0000x reference)
#include <cuda_runtime.h>
#include <cstdint>
#include <math.h>

#define B_  2
#define T_  2048
#define D_  1024
#define H_  16
#define DH  64

// ------------------------- scratch (__device__ globals) -------------------------
__device__ uint2 g_Qpk[B_*H_*T_*32];          // packed Q (scaled 1/8), [bh][t][j]
__device__ uint2 g_Kpk[B_*H_*T_*32];          // packed K
__device__ float g_V  [B_*H_*T_*DH];          // V float, per-head
__device__ uint2 g_Vpk[(size_t)B_*H_*DH*1024];// packed V^T, [bh][d][kp]
__device__ uint2 g_Apk[(size_t)B_*T_*512];    // packed attn output rows
__device__ uint2 g_qpk[(size_t)B_*T_*512];    // packed inputs
__device__ uint2 g_kpk[(size_t)B_*T_*512];
__device__ uint2 g_vpk[(size_t)B_*T_*512];
__device__ uint2 g_Wq[1024*512];
__device__ uint2 g_Wk[1024*512];
__device__ uint2 g_Wv[1024*512];
__device__ uint2 g_Wo[1024*512];

// ------------------------- helpers -------------------------
__device__ __forceinline__ uint32_t packbf(float x, float y) {
    uint32_t r; asm("cvt.rn.bf16x2.f32 %0, %1, %2;" : "=r"(r) : "f"(y), "f"(x)); return r;
}
__device__ __forceinline__ void split2(float x, float y, uint32_t& h, uint32_t& l) {
    h = packbf(x, y);
    float hx = __uint_as_float(h << 16);
    float hy = __uint_as_float(h & 0xFFFF0000u);
    l = packbf(x - hx, y - hy);
}
__device__ __forceinline__ void mma_bf16(float* d, const uint32_t* a, uint32_t b0, uint32_t b1) {
    asm volatile("mma.sync.aligned.m16n8k16.row.col.f32.bf16.bf16.f32 "
        "{%0,%1,%2,%3}, {%4,%5,%6,%7}, {%8,%9}, {%0,%1,%2,%3};"
        : "+f"(d[0]), "+f"(d[1]), "+f"(d[2]), "+f"(d[3])
        : "r"(a[0]), "r"(a[1]), "r"(a[2]), "r"(a[3]), "r"(b0), "r"(b1));
}
__device__ __forceinline__ uint32_t s2u(const void* p) {
    return (uint32_t)__cvta_generic_to_shared(p);
}
#define CP16(d, s) asm volatile("cp.async.cg.shared.global [%0], [%1], 16;" :: "r"(d), "l"(s))
#define CP8(d, s)  asm volatile("cp.async.ca.shared.global [%0], [%1], 8;"  :: "r"(d), "l"(s))
#define CP_COMMIT  asm volatile("cp.async.commit_group;" ::: "memory")
#define CP_WAIT1   asm volatile("cp.async.wait_group 1;" ::: "memory")
#define CP_WAIT0   asm volatile("cp.async.wait_group 0;" ::: "memory")

// ------------------------- prep: batched pack of all 7 tensors -------------------------
struct PackJob { const float* src; uint2* dst; int n2; };
__global__ __launch_bounds__(256) void pack_all(
    const float* q, const float* k, const float* v,
    const float* Wq, const float* Wk, const float* Wv, const float* Wo,
    uint2* qp, uint2* kp, uint2* vp, uint2* Wqp, uint2* Wkp, uint2* Wvp, uint2* Wop)
{
    // segments: 3 x 2M (inputs) + 4 x 512K (weights) = 8M uint2 total
    const int NI = 4096 * 512, NW = 1024 * 512;
    size_t gid = (size_t)blockIdx.x * 256 + threadIdx.x;
    const size_t stride = (size_t)gridDim.x * 256;
    const size_t total = 3 * (size_t)NI + 4 * (size_t)NW;
    for (size_t i = gid; i < total; i += stride) {
        const float* src; uint2* dst; size_t off;
        if (i < (size_t)NI)            { src = q;  dst = qp;  off = i; }
        else if (i < 2*(size_t)NI)     { src = k;  dst = kp;  off = i - NI; }
        else if (i < 3*(size_t)NI)     { src = v;  dst = vp;  off = i - 2*(size_t)NI; }
        else if (i < 3*(size_t)NI+NW)  { src = Wq; dst = Wqp; off = i - 3*(size_t)NI; }
        else if (i < 3*(size_t)NI+2*(size_t)NW) { src = Wk; dst = Wkp; off = i - 3*(size_t)NI - NW; }
        else if (i < 3*(size_t)NI+3*(size_t)NW) { src = Wv; dst = Wvp; off = i - 3*(size_t)NI - 2*(size_t)NW; }
        else                           { src = Wo; dst = Wop; off = i - 3*(size_t)NI - 3*(size_t)NW; }
        float2 vv = ((const float2*)src)[off];
        uint32_t h, l; split2(vv.x, vv.y, h, l);
        dst[off] = make_uint2(h, l);
    }
}

// ------------------------- prep: V float -> packed transposed -------------------------
__global__ __launch_bounds__(128) void v_pack(const float* __restrict__ V,
                                              uint2* __restrict__ Vpk)
{
    __shared__ float tile[64][65];
    const int tid = threadIdx.x;
    const int bh = blockIdx.y, kt = blockIdx.x * 64;
    const float* Vb = V + ((size_t)bh * 2048 + kt) * 64;
#pragma unroll
    for (int i = 0; i < 16; i++) {
        int idx = tid + i * 128;
        int r = idx >> 5, dp = idx & 31;
        float2 v = ((const float2*)Vb)[r * 32 + dp];
        tile[r][dp * 2] = v.x; tile[r][dp * 2 + 1] = v.y;
    }
    __syncthreads();
#pragma unroll
    for (int i = 0; i < 16; i++) {
        int idx = tid + i * 128;
        int d = idx >> 5, kp = idx & 31;
        uint32_t h, l; split2(tile[2 * kp][d], tile[2 * kp + 1][d], h, l);
        Vpk[((size_t)bh * 64 + d) * 1024 + (kt >> 1) + kp] = make_uint2(h, l);
    }
}

// ------------------------- GEMM mainloop (pre-packed, cp.async 2-stage) -------------------------
#define GS2 20
#define STAGE_U2 (128*GS2)

__device__ __forceinline__ void gemm_mainloop_pk(
    const uint2* __restrict__ Apk, const uint2* __restrict__ Wpk,
    int bm, int bn, uint2* Sa, uint2* Sb, float acc[4][4][4],
    int wm, int wn, int lr, int lc, int tid)
{
    const uint2* Abase = Apk + (size_t)bm * 512;
    const uint2* Bbase = Wpk + (size_t)bn * 512;

#define ISSUE(it_) do { \
    const int stage_ = (it_) & 1; \
    uint2* da_ = Sa + stage_ * STAGE_U2; \
    uint2* db_ = Sb + stage_ * STAGE_U2; \
    const uint2* As_ = Abase + (it_) * 16; \
    const uint2* Bs_ = Bbase + (it_) * 16; \
    _Pragma("unroll") \
    for (int t_ = 0; t_ < 4; t_++) { \
        int c_ = tid + t_ * 256; \
        int row_ = c_ >> 3, j_ = c_ & 7; \
        CP16(s2u(&da_[row_ * GS2 + 2 * j_]), &As_[(size_t)row_ * 512 + 2 * j_]); \
        CP16(s2u(&db_[row_ * GS2 + 2 * j_]), &Bs_[(size_t)row_ * 512 + 2 * j_]); \
    } \
} while(0)

    ISSUE(0); CP_COMMIT;
    for (int it = 0; it < 32; ++it) {
        if (it < 31) { ISSUE(it + 1); CP_COMMIT; CP_WAIT1; }
        else CP_WAIT0;
        __syncthreads();
        const uint2* sa = Sa + (it & 1) * STAGE_U2;
        const uint2* sb = Sb + (it & 1) * STAGE_U2;
#pragma unroll
        for (int c = 0; c < 2; ++c) {
            uint32_t ah[4][4], al[4][4];
#pragma unroll
            for (int mt = 0; mt < 4; ++mt) {
                const int r0 = wm + mt * 16 + lr;
                const int k0 = c * 8 + lc;
                uint2 u0 = sa[r0 * GS2 + k0];
                uint2 u1 = sa[(r0 + 8) * GS2 + k0];
                uint2 u2 = sa[r0 * GS2 + k0 + 4];
                uint2 u3 = sa[(r0 + 8) * GS2 + k0 + 4];
                ah[mt][0] = u0.x; ah[mt][1] = u1.x; ah[mt][2] = u2.x; ah[mt][3] = u3.x;
                al[mt][0] = u0.y; al[mt][1] = u1.y; al[mt][2] = u2.y; al[mt][3] = u3.y;
            }
#pragma unroll
            for (int nt = 0; nt < 4; ++nt) {
                const int cc = wn + nt * 8 + lr;
                const int k0 = c * 8 + lc;
                uint2 v0 = sb[cc * GS2 + k0];
                uint2 v1 = sb[cc * GS2 + k0 + 4];
#pragma unroll
                for (int mt = 0; mt < 4; ++mt) {
                    mma_bf16(acc[mt][nt], ah[mt], v0.x, v1.x);
                    mma_bf16(acc[mt][nt], ah[mt], v0.y, v1.y);
                    mma_bf16(acc[mt][nt], al[mt], v0.x, v1.x);
                }
            }
        }
        __syncthreads();
    }
#undef ISSUE
}

// ------------------------- fused QKV projection -------------------------
__global__ __launch_bounds__(256, 2) void gemm_qkv(
    const uint2* __restrict__ qpk, const uint2* __restrict__ kpk, const uint2* __restrict__ vpk,
    const uint2* __restrict__ Wq, const uint2* __restrict__ Wk, const uint2* __restrict__ Wv,
    uint2* __restrict__ Qpk, uint2* __restrict__ Kpk, float* __restrict__ Vf)
{
    extern __shared__ __align__(16) uint2 smemu[];
    uint2* Sa = smemu;
    uint2* Sb = smemu + 2 * STAGE_U2;

    const int which = blockIdx.x >> 3;
    const int bn = (blockIdx.x & 7) * 128;
    const int bm = blockIdx.y * 128;
    const uint2* A = which == 0 ? qpk : which == 1 ? kpk : vpk;
    const uint2* W = which == 0 ? Wq : which == 1 ? Wk : Wv;

    const int tid = threadIdx.x;
    const int wid = tid >> 5, lane = tid & 31;
    const int wm = (wid & 1) * 64, wn = (wid >> 1) * 32;
    const int lr = lane >> 2, lc = lane & 3;

    float acc[4][4][4];
#pragma unroll
    for (int mt = 0; mt < 4; mt++)
#pragma unroll
        for (int nt = 0; nt < 4; nt++)
#pragma unroll
            for (int i = 0; i < 4; i++) acc[mt][nt][i] = 0.f;

    gemm_mainloop_pk(A, W, bm, bn, Sa, Sb, acc, wm, wn, lr, lc, tid);

    if (which < 2) {
        uint2* P = which == 0 ? Qpk : Kpk;
        const float sc = which == 0 ? 0.125f : 1.0f;
#pragma unroll
        for (int mt = 0; mt < 4; ++mt)
#pragma unroll
            for (int nt = 0; nt < 4; ++nt) {
                const int row  = bm + wm + mt * 16 + lr;
                const int col0 = bn + wn + nt * 8 + lc * 2;
                const int hh = col0 >> 6, j = (col0 & 63) >> 1;
                const float* d = acc[mt][nt];
                uint32_t h, l;
                int b = row >> 11, t = row & 2047;
                split2(d[0] * sc, d[1] * sc, h, l);
                P[((size_t)(b * 16 + hh) * 2048 + t) * 32 + j] = make_uint2(h, l);
                b = (row + 8) >> 11; t = (row + 8) & 2047;
                split2(d[2] * sc, d[3] * sc, h, l);
                P[((size_t)(b * 16 + hh) * 2048 + t) * 32 + j] = make_uint2(h, l);
            }
    } else {
#pragma unroll
        for (int mt = 0; mt < 4; ++mt)
#pragma unroll
            for (int nt = 0; nt < 4; ++nt) {
                const int row  = bm + wm + mt * 16 + lr;
                const int col0 = bn + wn + nt * 8 + lc * 2;
                const int hh = col0 >> 6, dd = col0 & 63;
                const float* d = acc[mt][nt];
                int b = row >> 11, t = row & 2047;
                *(float2*)(Vf + (((size_t)(b * 16 + hh) * 2048 + t) * 64 + dd)) = make_float2(d[0], d[1]);
                b = (row + 8) >> 11; t = (row + 8) & 2047;
                *(float2*)(Vf + (((size_t)(b * 16 + hh) * 2048 + t) * 64 + dd)) = make_float2(d[2], d[3]);
            }
    }
}

// ------------------------- output projection -------------------------
__global__ __launch_bounds__(256, 2) void gemm_oproj(
    const uint2* __restrict__ Apk, const uint2* __restrict__ W, float* __restrict__ C)
{
    extern __shared__ __align__(16) uint2 smemu[];
    uint2* Sa = smemu;
    uint2* Sb = smemu + 2 * STAGE_U2;

    const int bn = blockIdx.x * 128;
    const int bm = blockIdx.y * 128;
    const int tid = threadIdx.x;
    const int wid = tid >> 5, lane = tid & 31;
    const int wm = (wid & 1) * 64, wn = (wid >> 1) * 32;
    const int lr = lane >> 2, lc = lane & 3;

    float acc[4][4][4];
#pragma unroll
    for (int mt = 0; mt < 4; mt++)
#pragma unroll
        for (int nt = 0; nt < 4; nt++)
#pragma unroll
            for (int i = 0; i < 4; i++) acc[mt][nt][i] = 0.f;

    gemm_mainloop_pk(Apk, W, bm, bn, Sa, Sb, acc, wm, wn, lr, lc, tid);

#pragma unroll
    for (int mt = 0; mt < 4; ++mt)
#pragma unroll
        for (int nt = 0; nt < 4; ++nt) {
            const int row  = bm + wm + mt * 16 + lr;
            const int col0 = bn + wn + nt * 8 + lc * 2;
            const float* d = acc[mt][nt];
            *(float2*)(C + (size_t)row * 1024 + col0)       = make_float2(d[0], d[1]);
            *(float2*)(C + (size_t)(row + 8) * 1024 + col0) = make_float2(d[2], d[3]);
        }
}

// ------------------------- flash attention: Br=128, 8 warps, cp.async 2-stage -------------------------
#define KS2 36
#define FSTG (64 * KS2)    // uint2 per K or V stage
__global__ __launch_bounds__(256, 2) void flash_attn4(
    const uint2* __restrict__ Qpk, const uint2* __restrict__ Kpk,
    const uint2* __restrict__ Vpk, const unsigned char* __restrict__ mask,
    uint2* __restrict__ Apk)
{
    extern __shared__ __align__(16) uint2 fsm[];
    uint2* SK = fsm;              // 2 stages
    uint2* SV = fsm + 2 * FSTG;   // 2 stages

    const int tid = threadIdx.x;
    const int w = tid >> 5, lane = tid & 31;
    const int lr = lane >> 2, lc = lane & 3;
    const int bh = blockIdx.y, b = bh >> 4, h = bh & 15;
    const int q0 = blockIdx.x * 128;
    const int t0 = q0 + w * 16;

    uint32_t qh[4][4], ql[4][4];
    {
        const uint2* q0p = Qpk + ((size_t)bh * 2048 + t0 + lr) * 32;
        const uint2* q1p = q0p + 8 * 32;
#pragma unroll
        for (int c = 0; c < 4; c++) {
            const int j = c * 8 + lc;
            uint2 u;
            u = q0p[j];     qh[c][0] = u.x; ql[c][0] = u.y;
            u = q1p[j];     qh[c][1] = u.x; ql[c][1] = u.y;
            u = q0p[j + 4]; qh[c][2] = u.x; ql[c][2] = u.y;
            u = q1p[j + 4]; qh[c][3] = u.x; ql[c][3] = u.y;
        }
    }

    float m0 = -1e30f, m1 = -1e30f, l0 = 0.f, l1 = 0.f;
    float o[8][4];
#pragma unroll
    for (int nt = 0; nt < 8; nt++)
#pragma unroll
        for (int i = 0; i < 4; i++) o[nt][i] = 0.f;

    const unsigned char* mrow0 = mask + ((size_t)b * 2048 + t0 + lr) * 2048;
    const unsigned char* mrow1 = mrow0 + 8 * 2048;

    const uint2* KB0 = Kpk + (size_t)bh * 2048 * 32;
    const uint2* VB0 = Vpk + (size_t)bh * 64 * 1024;

    // producer indices: K: 4 x 16B chunks; V: 8 x 8B
    const int kr = tid >> 2, kj = (tid & 3) * 8;       // K: row 0..63, j base
    const int vr = tid >> 2, vj0 = (tid & 3) * 8;      // V: row(d) 0..63

#define FISSUE(it_) do { \
    const int st_ = (it_) & 1; \
    const uint2* KB_ = KB0 + (size_t)(it_) * 64 * 32; \
    const uint2* VB_ = VB0 + (it_) * 32; \
    uint2* dk_ = SK + st_ * FSTG; \
    uint2* dv_ = SV + st_ * FSTG; \
    _Pragma("unroll") \
    for (int u_ = 0; u_ < 4; u_++) \
        CP16(s2u(&dk_[kr * KS2 + kj + 2 * u_]), &KB_[kr * 32 + kj + 2 * u_]); \
    const int sw_ = (vr >> 2) & 3; \
    _Pragma("unroll") \
    for (int u_ = 0; u_ < 8; u_++) { \
        int j_ = vj0 + u_; \
        CP8(s2u(&dv_[vr * KS2 + (j_ ^ sw_)]), &VB_[(size_t)vr * 1024 + j_]); \
    } \
} while(0)

    FISSUE(0); CP_COMMIT;

    for (int it = 0; it < 32; ++it) {
        if (it < 31) { FISSUE(it + 1); CP_COMMIT; CP_WAIT1; }
        else CP_WAIT0;
        __syncthreads();
        const uint2* sk = SK + (it & 1) * FSTG;
        const uint2* sv = SV + (it & 1) * FSTG;
        const int kt = it * 64;

        float s[8][4];
#pragma unroll
        for (int nt = 0; nt < 8; nt++)
#pragma unroll
            for (int i = 0; i < 4; i++) s[nt][i] = 0.f;
#pragma unroll
        for (int c = 0; c < 4; c++) {
#pragma unroll
            for (int nt = 0; nt < 8; nt++) {
                const int cc = nt * 8 + lr;
                const int k0 = c * 8 + lc;
                uint2 u0 = sk[cc * KS2 + k0];
                uint2 u1 = sk[cc * KS2 + k0 + 4];
                mma_bf16(s[nt], qh[c], u0.x, u1.x);
                mma_bf16(s[nt], qh[c], u0.y, u1.y);
                mma_bf16(s[nt], ql[c], u0.x, u1.x);
            }
        }

#pragma unroll
        for (int nt = 0; nt < 8; nt++) {
            const int cc = kt + nt * 8 + lc * 2;
            if (mrow0[cc])     s[nt][0] = -1e30f;
            if (mrow0[cc + 1]) s[nt][1] = -1e30f;
            if (mrow1[cc])     s[nt][2] = -1e30f;
            if (mrow1[cc + 1]) s[nt][3] = -1e30f;
        }

        float tm0 = -1e30f, tm1 = -1e30f;
#pragma unroll
        for (int nt = 0; nt < 8; nt++) {
            tm0 = fmaxf(tm0, fmaxf(s[nt][0], s[nt][1]));
            tm1 = fmaxf(tm1, fmaxf(s[nt][2], s[nt][3]));
        }
        tm0 = fmaxf(tm0, __shfl_xor_sync(0xffffffff, tm0, 1));
        tm0 = fmaxf(tm0, __shfl_xor_sync(0xffffffff, tm0, 2));
        tm1 = fmaxf(tm1, __shfl_xor_sync(0xffffffff, tm1, 1));
        tm1 = fmaxf(tm1, __shfl_xor_sync(0xffffffff, tm1, 2));
        float mn0 = fmaxf(m0, tm0), mn1 = fmaxf(m1, tm1);
        float cr0 = __expf(m0 - mn0), cr1 = __expf(m1 - mn1);
        m0 = mn0; m1 = mn1;
        float ts0 = 0.f, ts1 = 0.f;
#pragma unroll
        for (int nt = 0; nt < 8; nt++) {
            s[nt][0] = __expf(s[nt][0] - mn0);
            s[nt][1] = __expf(s[nt][1] - mn0);
            s[nt][2] = __expf(s[nt][2] - mn1);
            s[nt][3] = __expf(s[nt][3] - mn1);
            ts0 += s[nt][0] + s[nt][1];
            ts1 += s[nt][2] + s[nt][3];
        }
        ts0 += __shfl_xor_sync(0xffffffff, ts0, 1);
        ts0 += __shfl_xor_sync(0xffffffff, ts0, 2);
        ts1 += __shfl_xor_sync(0xffffffff, ts1, 1);
        ts1 += __shfl_xor_sync(0xffffffff, ts1, 2);
        l0 = l0 * cr0 + ts0;
        l1 = l1 * cr1 + ts1;
#pragma unroll
        for (int nt = 0; nt < 8; nt++) {
            o[nt][0] *= cr0; o[nt][1] *= cr0;
            o[nt][2] *= cr1; o[nt][3] *= cr1;
        }

#pragma unroll
        for (int kc = 0; kc < 4; kc++) {
            uint32_t ph[4], pl[4];
            split2(s[2*kc][0],   s[2*kc][1],   ph[0], pl[0]);
            split2(s[2*kc][2],   s[2*kc][3],   ph[1], pl[1]);
            split2(s[2*kc+1][0], s[2*kc+1][1], ph[2], pl[2]);
            split2(s[2*kc+1][2], s[2*kc+1][3], ph[3], pl[3]);
#pragma unroll
            for (int nt = 0; nt < 8; nt++) {
                const int n = nt * 8 + lr;
                const int x = (n >> 2) & 3;
                const int j0 = kc * 8 + lc;
                uint2 u0 = sv[n * KS2 + (j0 ^ x)];
                uint2 u1 = sv[n * KS2 + ((j0 + 4) ^ x)];
                mma_bf16(o[nt], ph, u0.x, u1.x);
                mma_bf16(o[nt], ph, u0.y, u1.y);
                mma_bf16(o[nt], pl, u0.x, u1.x);
            }
        }
        __syncthreads();
    }

    const float inv0 = 1.f / l0, inv1 = 1.f / l1;
    uint2* A0 = Apk + ((size_t)b * 2048 + t0 + lr) * 512 + h * 32;
    uint2* A1 = A0 + 8 * 512;
#pragma unroll
    for (int nt = 0; nt < 8; nt++) {
        const int j = nt * 4 + lc;
        uint32_t hh, ll;
        split2(o[nt][0] * inv0, o[nt][1] * inv0, hh, ll);
        A0[j] = make_uint2(hh, ll);
        split2(o[nt][2] * inv1, o[nt][3] * inv1, hh, ll);
        A1[j] = make_uint2(hh, ll);
    }
}

extern "C" void kernel_launch(void* const* d_in, const int* in_sizes, int n_in,
                              void* d_out, int out_size)
{
    const float* query = (const float*)d_in[0];
    const float* key   = (const float*)d_in[1];
    const float* value = (const float*)d_in[2];
    const unsigned char* mask = (const unsigned char*)d_in[3];
    const float* Wq = (const float*)d_in[4];
    const float* Wk = (const float*)d_in[5];
    const float* Wv = (const float*)d_in[6];
    const float* Wo = (const float*)d_in[7];

    void *pQpk, *pKpk, *pV, *pVpk, *pApk, *pqpk, *pkpk, *pvpk, *pWq, *pWk, *pWv, *pWo;
    cudaGetSymbolAddress(&pQpk, g_Qpk);
    cudaGetSymbolAddress(&pKpk, g_Kpk);
    cudaGetSymbolAddress(&pV,   g_V);
    cudaGetSymbolAddress(&pVpk, g_Vpk);
    cudaGetSymbolAddress(&pApk, g_Apk);
    cudaGetSymbolAddress(&pqpk, g_qpk);
    cudaGetSymbolAddress(&pkpk, g_kpk);
    cudaGetSymbolAddress(&pvpk, g_vpk);
    cudaGetSymbolAddress(&pWq,  g_Wq);
    cudaGetSymbolAddress(&pWk,  g_Wk);
    cudaGetSymbolAddress(&pWv,  g_Wv);
    cudaGetSymbolAddress(&pWo,  g_Wo);

    const int SMEM_GEMM  = 4 * STAGE_U2 * 8;   // 81920 B
    const int SMEM_FLASH = 4 * FSTG * 8;       // 73728 B
    cudaFuncSetAttribute(gemm_qkv,   cudaFuncAttributeMaxDynamicSharedMemorySize, SMEM_GEMM);
    cudaFuncSetAttribute(gemm_oproj, cudaFuncAttributeMaxDynamicSharedMemorySize, SMEM_GEMM);
    cudaFuncSetAttribute(flash_attn4, cudaFuncAttributeMaxDynamicSharedMemorySize, SMEM_FLASH);

    pack_all<<<2048, 256>>>(query, key, value, Wq, Wk, Wv, Wo,
        (uint2*)pqpk, (uint2*)pkpk, (uint2*)pvpk,
        (uint2*)pWq, (uint2*)pWk, (uint2*)pWv, (uint2*)pWo);

    dim3 gq(24, 32);
    gemm_qkv<<<gq, 256, SMEM_GEMM>>>((const uint2*)pqpk, (const uint2*)pkpk, (const uint2*)pvpk,
                                     (const uint2*)pWq, (const uint2*)pWk, (const uint2*)pWv,
                                     (uint2*)pQpk, (uint2*)pKpk, (float*)pV);

    dim3 gv(32, 32);
    v_pack<<<gv, 128>>>((const float*)pV, (uint2*)pVpk);

    dim3 ga(T_ / 128, B_ * H_);       // (16, 32)
    flash_attn4<<<ga, 256, SMEM_FLASH>>>((const uint2*)pQpk, (const uint2*)pKpk,
                                         (const uint2*)pVpk, mask, (uint2*)pApk);

    dim3 go(8, 32);
    gemm_oproj<<<go, 256, SMEM_GEMM>>>((const uint2*)pApk, (const uint2*)pWo, (float*)d_out);
}

// round 8
// speedup vs baseline: 1.1948x; 1.1948x over previous
#include <cuda_runtime.h>
#include <cstdint>
#include <math.h>

#define B_  2
#define T_  2048
#define D_  1024
#define H_  16
#define DH  64

// ------------------------- scratch (__device__ globals) -------------------------
__device__ uint2 g_Qpk[B_*H_*T_*32];          // packed Q (scaled 1/8), [bh][t][j]
__device__ uint2 g_Kpk[B_*H_*T_*32];          // packed K
__device__ float g_V  [B_*H_*T_*DH];          // V float, per-head
__device__ uint2 g_Vpk[(size_t)B_*H_*DH*1024];// packed V^T, [bh][d][kp]
__device__ uint2 g_Apk[(size_t)B_*T_*512];    // packed attn output rows
__device__ uint2 g_qpk[(size_t)B_*T_*512];    // packed inputs
__device__ uint2 g_kpk[(size_t)B_*T_*512];
__device__ uint2 g_vpk[(size_t)B_*T_*512];
__device__ uint2 g_Wq[1024*512];
__device__ uint2 g_Wk[1024*512];
__device__ uint2 g_Wv[1024*512];
__device__ uint2 g_Wo[1024*512];
__device__ int   g_mask_any;

// ------------------------- helpers -------------------------
__device__ __forceinline__ uint32_t packbf(float x, float y) {
    uint32_t r; asm("cvt.rn.bf16x2.f32 %0, %1, %2;" : "=r"(r) : "f"(y), "f"(x)); return r;
}
__device__ __forceinline__ void split2(float x, float y, uint32_t& h, uint32_t& l) {
    h = packbf(x, y);
    float hx = __uint_as_float(h << 16);
    float hy = __uint_as_float(h & 0xFFFF0000u);
    l = packbf(x - hx, y - hy);
}
__device__ __forceinline__ void mma_bf16(float* d, const uint32_t* a, uint32_t b0, uint32_t b1) {
    asm volatile("mma.sync.aligned.m16n8k16.row.col.f32.bf16.bf16.f32 "
        "{%0,%1,%2,%3}, {%4,%5,%6,%7}, {%8,%9}, {%0,%1,%2,%3};"
        : "+f"(d[0]), "+f"(d[1]), "+f"(d[2]), "+f"(d[3])
        : "r"(a[0]), "r"(a[1]), "r"(a[2]), "r"(a[3]), "r"(b0), "r"(b1));
}
__device__ __forceinline__ uint32_t s2u(const void* p) {
    return (uint32_t)__cvta_generic_to_shared(p);
}
#define CP16(d, s) asm volatile("cp.async.cg.shared.global [%0], [%1], 16;" :: "r"(d), "l"(s))
#define CP_COMMIT  asm volatile("cp.async.commit_group;" ::: "memory")
#define CP_WAIT1   asm volatile("cp.async.wait_group 1;" ::: "memory")
#define CP_WAIT0   asm volatile("cp.async.wait_group 0;" ::: "memory")

// ------------------------- prep: mask-any scan -------------------------
__global__ void zero_flag() { g_mask_any = 0; }
__global__ __launch_bounds__(256) void mask_scan(const uint4* __restrict__ m, int n4)
{
    uint32_t acc = 0;
    for (int i = blockIdx.x * 256 + threadIdx.x; i < n4; i += gridDim.x * 256) {
        uint4 v = m[i];
        acc |= v.x | v.y | v.z | v.w;
    }
    acc |= __shfl_xor_sync(0xffffffff, acc, 16);
    acc |= __shfl_xor_sync(0xffffffff, acc, 8);
    acc |= __shfl_xor_sync(0xffffffff, acc, 4);
    acc |= __shfl_xor_sync(0xffffffff, acc, 2);
    acc |= __shfl_xor_sync(0xffffffff, acc, 1);
    if ((threadIdx.x & 31) == 0 && acc) atomicOr(&g_mask_any, 1);
}

// ------------------------- prep: batched pack of all 7 tensors -------------------------
__global__ __launch_bounds__(256) void pack_all(
    const float* q, const float* k, const float* v,
    const float* Wq, const float* Wk, const float* Wv, const float* Wo,
    uint2* qp, uint2* kp, uint2* vp, uint2* Wqp, uint2* Wkp, uint2* Wvp, uint2* Wop)
{
    const int NI = 4096 * 512, NW = 1024 * 512;
    size_t gid = (size_t)blockIdx.x * 256 + threadIdx.x;
    const size_t stride = (size_t)gridDim.x * 256;
    const size_t total = 3 * (size_t)NI + 4 * (size_t)NW;
    for (size_t i = gid; i < total; i += stride) {
        const float* src; uint2* dst; size_t off;
        if (i < (size_t)NI)            { src = q;  dst = qp;  off = i; }
        else if (i < 2*(size_t)NI)     { src = k;  dst = kp;  off = i - NI; }
        else if (i < 3*(size_t)NI)     { src = v;  dst = vp;  off = i - 2*(size_t)NI; }
        else if (i < 3*(size_t)NI+NW)  { src = Wq; dst = Wqp; off = i - 3*(size_t)NI; }
        else if (i < 3*(size_t)NI+2*(size_t)NW) { src = Wk; dst = Wkp; off = i - 3*(size_t)NI - NW; }
        else if (i < 3*(size_t)NI+3*(size_t)NW) { src = Wv; dst = Wvp; off = i - 3*(size_t)NI - 2*(size_t)NW; }
        else                           { src = Wo; dst = Wop; off = i - 3*(size_t)NI - 3*(size_t)NW; }
        float2 vv = ((const float2*)src)[off];
        uint32_t h, l; split2(vv.x, vv.y, h, l);
        dst[off] = make_uint2(h, l);
    }
}

// ------------------------- prep: V float -> packed transposed -------------------------
__global__ __launch_bounds__(128) void v_pack(const float* __restrict__ V,
                                              uint2* __restrict__ Vpk)
{
    __shared__ float tile[64][65];
    const int tid = threadIdx.x;
    const int bh = blockIdx.y, kt = blockIdx.x * 64;
    const float* Vb = V + ((size_t)bh * 2048 + kt) * 64;
#pragma unroll
    for (int i = 0; i < 16; i++) {
        int idx = tid + i * 128;
        int r = idx >> 5, dp = idx & 31;
        float2 v = ((const float2*)Vb)[r * 32 + dp];
        tile[r][dp * 2] = v.x; tile[r][dp * 2 + 1] = v.y;
    }
    __syncthreads();
#pragma unroll
    for (int i = 0; i < 16; i++) {
        int idx = tid + i * 128;
        int d = idx >> 5, kp = idx & 31;
        uint32_t h, l; split2(tile[2 * kp][d], tile[2 * kp + 1][d], h, l);
        Vpk[((size_t)bh * 64 + d) * 1024 + (kt >> 1) + kp] = make_uint2(h, l);
    }
}

// ------------------------- GEMM mainloop (pre-packed, cp.async 2-stage) -------------------------
#define GS2 20
#define STAGE_U2 (128*GS2)

__device__ __forceinline__ void gemm_mainloop_pk(
    const uint2* __restrict__ Apk, const uint2* __restrict__ Wpk,
    int bm, int bn, uint2* Sa, uint2* Sb, float acc[4][4][4],
    int wm, int wn, int lr, int lc, int tid)
{
    const uint2* Abase = Apk + (size_t)bm * 512;
    const uint2* Bbase = Wpk + (size_t)bn * 512;

#define ISSUE(it_) do { \
    const int stage_ = (it_) & 1; \
    uint2* da_ = Sa + stage_ * STAGE_U2; \
    uint2* db_ = Sb + stage_ * STAGE_U2; \
    const uint2* As_ = Abase + (it_) * 16; \
    const uint2* Bs_ = Bbase + (it_) * 16; \
    _Pragma("unroll") \
    for (int t_ = 0; t_ < 4; t_++) { \
        int c_ = tid + t_ * 256; \
        int row_ = c_ >> 3, j_ = c_ & 7; \
        CP16(s2u(&da_[row_ * GS2 + 2 * j_]), &As_[(size_t)row_ * 512 + 2 * j_]); \
        CP16(s2u(&db_[row_ * GS2 + 2 * j_]), &Bs_[(size_t)row_ * 512 + 2 * j_]); \
    } \
} while(0)

    ISSUE(0); CP_COMMIT;
    for (int it = 0; it < 32; ++it) {
        if (it < 31) { ISSUE(it + 1); CP_COMMIT; CP_WAIT1; }
        else CP_WAIT0;
        __syncthreads();
        const uint2* sa = Sa + (it & 1) * STAGE_U2;
        const uint2* sb = Sb + (it & 1) * STAGE_U2;
#pragma unroll
        for (int c = 0; c < 2; ++c) {
            uint32_t ah[4][4], al[4][4];
#pragma unroll
            for (int mt = 0; mt < 4; ++mt) {
                const int r0 = wm + mt * 16 + lr;
                const int k0 = c * 8 + lc;
                uint2 u0 = sa[r0 * GS2 + k0];
                uint2 u1 = sa[(r0 + 8) * GS2 + k0];
                uint2 u2 = sa[r0 * GS2 + k0 + 4];
                uint2 u3 = sa[(r0 + 8) * GS2 + k0 + 4];
                ah[mt][0] = u0.x; ah[mt][1] = u1.x; ah[mt][2] = u2.x; ah[mt][3] = u3.x;
                al[mt][0] = u0.y; al[mt][1] = u1.y; al[mt][2] = u2.y; al[mt][3] = u3.y;
            }
#pragma unroll
            for (int nt = 0; nt < 4; ++nt) {
                const int cc = wn + nt * 8 + lr;
                const int k0 = c * 8 + lc;
                uint2 v0 = sb[cc * GS2 + k0];
                uint2 v1 = sb[cc * GS2 + k0 + 4];
#pragma unroll
                for (int mt = 0; mt < 4; ++mt) {
                    mma_bf16(acc[mt][nt], ah[mt], v0.x, v1.x);
                    mma_bf16(acc[mt][nt], ah[mt], v0.y, v1.y);
                    mma_bf16(acc[mt][nt], al[mt], v0.x, v1.x);
                }
            }
        }
        __syncthreads();
    }
#undef ISSUE
}

// ------------------------- fused QKV projection -------------------------
__global__ __launch_bounds__(256, 2) void gemm_qkv(
    const uint2* __restrict__ qpk, const uint2* __restrict__ kpk, const uint2* __restrict__ vpk,
    const uint2* __restrict__ Wq, const uint2* __restrict__ Wk, const uint2* __restrict__ Wv,
    uint2* __restrict__ Qpk, uint2* __restrict__ Kpk, float* __restrict__ Vf)
{
    extern __shared__ __align__(16) uint2 smemu[];
    uint2* Sa = smemu;
    uint2* Sb = smemu + 2 * STAGE_U2;

    const int which = blockIdx.x >> 3;
    const int bn = (blockIdx.x & 7) * 128;
    const int bm = blockIdx.y * 128;
    const uint2* A = which == 0 ? qpk : which == 1 ? kpk : vpk;
    const uint2* W = which == 0 ? Wq : which == 1 ? Wk : Wv;

    const int tid = threadIdx.x;
    const int wid = tid >> 5, lane = tid & 31;
    const int wm = (wid & 1) * 64, wn = (wid >> 1) * 32;
    const int lr = lane >> 2, lc = lane & 3;

    float acc[4][4][4];
#pragma unroll
    for (int mt = 0; mt < 4; mt++)
#pragma unroll
        for (int nt = 0; nt < 4; nt++)
#pragma unroll
            for (int i = 0; i < 4; i++) acc[mt][nt][i] = 0.f;

    gemm_mainloop_pk(A, W, bm, bn, Sa, Sb, acc, wm, wn, lr, lc, tid);

    if (which < 2) {
        uint2* P = which == 0 ? Qpk : Kpk;
        const float sc = which == 0 ? 0.125f : 1.0f;
#pragma unroll
        for (int mt = 0; mt < 4; ++mt)
#pragma unroll
            for (int nt = 0; nt < 4; ++nt) {
                const int row  = bm + wm + mt * 16 + lr;
                const int col0 = bn + wn + nt * 8 + lc * 2;
                const int hh = col0 >> 6, j = (col0 & 63) >> 1;
                const float* d = acc[mt][nt];
                uint32_t h, l;
                int b = row >> 11, t = row & 2047;
                split2(d[0] * sc, d[1] * sc, h, l);
                P[((size_t)(b * 16 + hh) * 2048 + t) * 32 + j] = make_uint2(h, l);
                b = (row + 8) >> 11; t = (row + 8) & 2047;
                split2(d[2] * sc, d[3] * sc, h, l);
                P[((size_t)(b * 16 + hh) * 2048 + t) * 32 + j] = make_uint2(h, l);
            }
    } else {
#pragma unroll
        for (int mt = 0; mt < 4; ++mt)
#pragma unroll
            for (int nt = 0; nt < 4; ++nt) {
                const int row  = bm + wm + mt * 16 + lr;
                const int col0 = bn + wn + nt * 8 + lc * 2;
                const int hh = col0 >> 6, dd = col0 & 63;
                const float* d = acc[mt][nt];
                int b = row >> 11, t = row & 2047;
                *(float2*)(Vf + (((size_t)(b * 16 + hh) * 2048 + t) * 64 + dd)) = make_float2(d[0], d[1]);
                b = (row + 8) >> 11; t = (row + 8) & 2047;
                *(float2*)(Vf + (((size_t)(b * 16 + hh) * 2048 + t) * 64 + dd)) = make_float2(d[2], d[3]);
            }
    }
}

// ------------------------- output projection -------------------------
__global__ __launch_bounds__(256, 2) void gemm_oproj(
    const uint2* __restrict__ Apk, const uint2* __restrict__ W, float* __restrict__ C)
{
    extern __shared__ __align__(16) uint2 smemu[];
    uint2* Sa = smemu;
    uint2* Sb = smemu + 2 * STAGE_U2;

    const int bn = blockIdx.x * 128;
    const int bm = blockIdx.y * 128;
    const int tid = threadIdx.x;
    const int wid = tid >> 5, lane = tid & 31;
    const int wm = (wid & 1) * 64, wn = (wid >> 1) * 32;
    const int lr = lane >> 2, lc = lane & 3;

    float acc[4][4][4];
#pragma unroll
    for (int mt = 0; mt < 4; mt++)
#pragma unroll
        for (int nt = 0; nt < 4; nt++)
#pragma unroll
            for (int i = 0; i < 4; i++) acc[mt][nt][i] = 0.f;

    gemm_mainloop_pk(Apk, W, bm, bn, Sa, Sb, acc, wm, wn, lr, lc, tid);

#pragma unroll
    for (int mt = 0; mt < 4; ++mt)
#pragma unroll
        for (int nt = 0; nt < 4; ++nt) {
            const int row  = bm + wm + mt * 16 + lr;
            const int col0 = bn + wn + nt * 8 + lc * 2;
            const float* d = acc[mt][nt];
            *(float2*)(C + (size_t)row * 1024 + col0)       = make_float2(d[0], d[1]);
            *(float2*)(C + (size_t)(row + 8) * 1024 + col0) = make_float2(d[2], d[3]);
        }
}

// ------------------------- flash attention (R6 structure + mask fast path) -------------------------
#define KS2 36
__global__ __launch_bounds__(128, 4) void flash_attn5(
    const uint2* __restrict__ Qpk, const uint2* __restrict__ Kpk,
    const uint2* __restrict__ Vpk, const unsigned char* __restrict__ mask,
    uint2* __restrict__ Apk)
{
    __shared__ __align__(16) uint2 SK[64 * KS2];
    __shared__ __align__(16) uint2 SV[64 * KS2];

    const int tid = threadIdx.x;
    const int w = tid >> 5, lane = tid & 31;
    const int lr = lane >> 2, lc = lane & 3;
    const int bh = blockIdx.y, b = bh >> 4, h = bh & 15;
    const int q0 = blockIdx.x * 64;
    const int t0 = q0 + w * 16;
    const bool anymask = (g_mask_any != 0);

    uint32_t qh[4][4], ql[4][4];
    {
        const uint2* q0p = Qpk + ((size_t)bh * 2048 + t0 + lr) * 32;
        const uint2* q1p = q0p + 8 * 32;
#pragma unroll
        for (int c = 0; c < 4; c++) {
            const int j = c * 8 + lc;
            uint2 u;
            u = q0p[j];     qh[c][0] = u.x; ql[c][0] = u.y;
            u = q1p[j];     qh[c][1] = u.x; ql[c][1] = u.y;
            u = q0p[j + 4]; qh[c][2] = u.x; ql[c][2] = u.y;
            u = q1p[j + 4]; qh[c][3] = u.x; ql[c][3] = u.y;
        }
    }

    float m0 = -1e30f, m1 = -1e30f, l0 = 0.f, l1 = 0.f;
    float o[8][4];
#pragma unroll
    for (int nt = 0; nt < 8; nt++)
#pragma unroll
        for (int i = 0; i < 4; i++) o[nt][i] = 0.f;

    const unsigned char* mrow0 = mask + ((size_t)b * 2048 + t0 + lr) * 2048;
    const unsigned char* mrow1 = mrow0 + 8 * 2048;

    for (int kt = 0; kt < 2048; kt += 64) {
        __syncthreads();
        {   // producers: pure copies of pre-packed data
            const uint2* KB = Kpk + ((size_t)bh * 2048 + kt) * 32;
            const uint2* VB = Vpk + (size_t)bh * 64 * 1024 + (kt >> 1);
#pragma unroll
            for (int i = 0; i < 16; i++) {
                int idx = tid + i * 128;
                int r = idx >> 5, j = idx & 31;
                SK[r * KS2 + j] = KB[r * 32 + j];
                SV[r * KS2 + (j ^ ((r >> 2) & 3))] = VB[(size_t)r * 1024 + j];
            }
        }
        __syncthreads();

        float s[8][4];
#pragma unroll
        for (int nt = 0; nt < 8; nt++)
#pragma unroll
            for (int i = 0; i < 4; i++) s[nt][i] = 0.f;
#pragma unroll
        for (int c = 0; c < 4; c++) {
#pragma unroll
            for (int nt = 0; nt < 8; nt++) {
                const int cc = nt * 8 + lr;
                const int k0 = c * 8 + lc;
                uint2 u0 = SK[cc * KS2 + k0];
                uint2 u1 = SK[cc * KS2 + k0 + 4];
                mma_bf16(s[nt], qh[c], u0.x, u1.x);
                mma_bf16(s[nt], qh[c], u0.y, u1.y);
                mma_bf16(s[nt], ql[c], u0.x, u1.x);
            }
        }

        if (anymask) {
#pragma unroll
            for (int nt = 0; nt < 8; nt++) {
                const int cc = kt + nt * 8 + lc * 2;
                if (mrow0[cc])     s[nt][0] = -1e30f;
                if (mrow0[cc + 1]) s[nt][1] = -1e30f;
                if (mrow1[cc])     s[nt][2] = -1e30f;
                if (mrow1[cc + 1]) s[nt][3] = -1e30f;
            }
        }

        float tm0 = -1e30f, tm1 = -1e30f;
#pragma unroll
        for (int nt = 0; nt < 8; nt++) {
            tm0 = fmaxf(tm0, fmaxf(s[nt][0], s[nt][1]));
            tm1 = fmaxf(tm1, fmaxf(s[nt][2], s[nt][3]));
        }
        tm0 = fmaxf(tm0, __shfl_xor_sync(0xffffffff, tm0, 1));
        tm0 = fmaxf(tm0, __shfl_xor_sync(0xffffffff, tm0, 2));
        tm1 = fmaxf(tm1, __shfl_xor_sync(0xffffffff, tm1, 1));
        tm1 = fmaxf(tm1, __shfl_xor_sync(0xffffffff, tm1, 2));
        float mn0 = fmaxf(m0, tm0), mn1 = fmaxf(m1, tm1);
        float cr0 = __expf(m0 - mn0), cr1 = __expf(m1 - mn1);
        m0 = mn0; m1 = mn1;
        float ts0 = 0.f, ts1 = 0.f;
#pragma unroll
        for (int nt = 0; nt < 8; nt++) {
            s[nt][0] = __expf(s[nt][0] - mn0);
            s[nt][1] = __expf(s[nt][1] - mn0);
            s[nt][2] = __expf(s[nt][2] - mn1);
            s[nt][3] = __expf(s[nt][3] - mn1);
            ts0 += s[nt][0] + s[nt][1];
            ts1 += s[nt][2] + s[nt][3];
        }
        ts0 += __shfl_xor_sync(0xffffffff, ts0, 1);
        ts0 += __shfl_xor_sync(0xffffffff, ts0, 2);
        ts1 += __shfl_xor_sync(0xffffffff, ts1, 1);
        ts1 += __shfl_xor_sync(0xffffffff, ts1, 2);
        l0 = l0 * cr0 + ts0;
        l1 = l1 * cr1 + ts1;
#pragma unroll
        for (int nt = 0; nt < 8; nt++) {
            o[nt][0] *= cr0; o[nt][1] *= cr0;
            o[nt][2] *= cr1; o[nt][3] *= cr1;
        }

#pragma unroll
        for (int kc = 0; kc < 4; kc++) {
            uint32_t ph[4], pl[4];
            split2(s[2*kc][0],   s[2*kc][1],   ph[0], pl[0]);
            split2(s[2*kc][2],   s[2*kc][3],   ph[1], pl[1]);
            split2(s[2*kc+1][0], s[2*kc+1][1], ph[2], pl[2]);
            split2(s[2*kc+1][2], s[2*kc+1][3], ph[3], pl[3]);
#pragma unroll
            for (int nt = 0; nt < 8; nt++) {
                const int n = nt * 8 + lr;
                const int x = (n >> 2) & 3;
                const int j0 = kc * 8 + lc;
                uint2 u0 = SV[n * KS2 + (j0 ^ x)];
                uint2 u1 = SV[n * KS2 + ((j0 + 4) ^ x)];
                mma_bf16(o[nt], ph, u0.x, u1.x);
                mma_bf16(o[nt], ph, u0.y, u1.y);
                mma_bf16(o[nt], pl, u0.x, u1.x);
            }
        }
    }

    const float inv0 = 1.f / l0, inv1 = 1.f / l1;
    uint2* A0 = Apk + ((size_t)b * 2048 + t0 + lr) * 512 + h * 32;
    uint2* A1 = A0 + 8 * 512;
#pragma unroll
    for (int nt = 0; nt < 8; nt++) {
        const int j = nt * 4 + lc;
        uint32_t hh, ll;
        split2(o[nt][0] * inv0, o[nt][1] * inv0, hh, ll);
        A0[j] = make_uint2(hh, ll);
        split2(o[nt][2] * inv1, o[nt][3] * inv1, hh, ll);
        A1[j] = make_uint2(hh, ll);
    }
}

extern "C" void kernel_launch(void* const* d_in, const int* in_sizes, int n_in,
                              void* d_out, int out_size)
{
    const float* query = (const float*)d_in[0];
    const float* key   = (const float*)d_in[1];
    const float* value = (const float*)d_in[2];
    const unsigned char* mask = (const unsigned char*)d_in[3];
    const float* Wq = (const float*)d_in[4];
    const float* Wk = (const float*)d_in[5];
    const float* Wv = (const float*)d_in[6];
    const float* Wo = (const float*)d_in[7];

    void *pQpk, *pKpk, *pV, *pVpk, *pApk, *pqpk, *pkpk, *pvpk, *pWq, *pWk, *pWv, *pWo;
    cudaGetSymbolAddress(&pQpk, g_Qpk);
    cudaGetSymbolAddress(&pKpk, g_Kpk);
    cudaGetSymbolAddress(&pV,   g_V);
    cudaGetSymbolAddress(&pVpk, g_Vpk);
    cudaGetSymbolAddress(&pApk, g_Apk);
    cudaGetSymbolAddress(&pqpk, g_qpk);
    cudaGetSymbolAddress(&pkpk, g_kpk);
    cudaGetSymbolAddress(&pvpk, g_vpk);
    cudaGetSymbolAddress(&pWq,  g_Wq);
    cudaGetSymbolAddress(&pWk,  g_Wk);
    cudaGetSymbolAddress(&pWv,  g_Wv);
    cudaGetSymbolAddress(&pWo,  g_Wo);

    const int SMEM_GEMM = 4 * STAGE_U2 * 8;   // 81920 B
    cudaFuncSetAttribute(gemm_qkv,   cudaFuncAttributeMaxDynamicSharedMemorySize, SMEM_GEMM);
    cudaFuncSetAttribute(gemm_oproj, cudaFuncAttributeMaxDynamicSharedMemorySize, SMEM_GEMM);

    zero_flag<<<1, 1>>>();
    mask_scan<<<256, 256>>>((const uint4*)mask, (B_ * T_ * T_) / 16);

    pack_all<<<2048, 256>>>(query, key, value, Wq, Wk, Wv, Wo,
        (uint2*)pqpk, (uint2*)pkpk, (uint2*)pvpk,
        (uint2*)pWq, (uint2*)pWk, (uint2*)pWv, (uint2*)pWo);

    dim3 gq(24, 32);
    gemm_qkv<<<gq, 256, SMEM_GEMM>>>((const uint2*)pqpk, (const uint2*)pkpk, (const uint2*)pvpk,
                                     (const uint2*)pWq, (const uint2*)pWk, (const uint2*)pWv,
                                     (uint2*)pQpk, (uint2*)pKpk, (float*)pV);

    dim3 gv(32, 32);
    v_pack<<<gv, 128>>>((const float*)pV, (uint2*)pVpk);

    dim3 ga(T_ / 64, B_ * H_);        // (32, 32)
    flash_attn5<<<ga, 128>>>((const uint2*)pQpk, (const uint2*)pKpk,
                             (const uint2*)pVpk, mask, (uint2*)pApk);

    dim3 go(8, 32);
    gemm_oproj<<<go, 256, SMEM_GEMM>>>((const uint2*)pApk, (const uint2*)pWo, (float*)d_out);
}

// round 9
// speedup vs baseline: 1.2735x; 1.0659x over previous
#include <cuda_runtime.h>
#include <cstdint>
#include <math.h>

#define B_  2
#define T_  2048
#define D_  1024
#define H_  16
#define DH  64

// ------------------------- scratch: hi/lo plane globals -------------------------
// GEMM inputs (rows x 512 words per plane)
__device__ uint32_t g_qh[4096*512], g_ql[4096*512];
__device__ uint32_t g_kh[4096*512], g_kl[4096*512];
__device__ uint32_t g_vh[4096*512], g_vl[4096*512];
__device__ uint32_t g_Wqh[1024*512], g_Wql[1024*512];
__device__ uint32_t g_Wkh[1024*512], g_Wkl[1024*512];
__device__ uint32_t g_Wvh[1024*512], g_Wvl[1024*512];
__device__ uint32_t g_Woh[1024*512], g_Wol[1024*512];
// attention operands
__device__ uint2    g_Qpk[B_*H_*T_*32];            // Q interleaved (scaled by log2e/8)
__device__ uint32_t g_Kh[B_*H_*T_*32], g_Kl[B_*H_*T_*32];   // [bh][t][32]
__device__ float    g_V [B_*H_*T_*DH];
__device__ uint32_t g_Vh[(size_t)B_*H_*DH*1024], g_Vl[(size_t)B_*H_*DH*1024]; // [bh][d][kp]
__device__ uint32_t g_Ah[(size_t)4096*512], g_Al[(size_t)4096*512];           // attn out planes
__device__ int      g_mask_any;

// ------------------------- helpers -------------------------
__device__ __forceinline__ uint32_t packbf(float x, float y) {
    uint32_t r; asm("cvt.rn.bf16x2.f32 %0, %1, %2;" : "=r"(r) : "f"(y), "f"(x)); return r;
}
__device__ __forceinline__ void split2(float x, float y, uint32_t& h, uint32_t& l) {
    h = packbf(x, y);
    float hx = __uint_as_float(h << 16);
    float hy = __uint_as_float(h & 0xFFFF0000u);
    l = packbf(x - hx, y - hy);
}
__device__ __forceinline__ void mma_bf16(float* d, const uint32_t* a, uint32_t b0, uint32_t b1) {
    asm volatile("mma.sync.aligned.m16n8k16.row.col.f32.bf16.bf16.f32 "
        "{%0,%1,%2,%3}, {%4,%5,%6,%7}, {%8,%9}, {%0,%1,%2,%3};"
        : "+f"(d[0]), "+f"(d[1]), "+f"(d[2]), "+f"(d[3])
        : "r"(a[0]), "r"(a[1]), "r"(a[2]), "r"(a[3]), "r"(b0), "r"(b1));
}
__device__ __forceinline__ void ldx4(uint32_t* r, uint32_t addr) {
    asm volatile("ldmatrix.sync.aligned.m8n8.x4.shared.b16 {%0,%1,%2,%3}, [%4];"
        : "=r"(r[0]), "=r"(r[1]), "=r"(r[2]), "=r"(r[3]) : "r"(addr));
}
__device__ __forceinline__ float ex2(float x) {
    float y; asm("ex2.approx.f32 %0, %1;" : "=f"(y) : "f"(x)); return y;
}
__device__ __forceinline__ uint32_t s2u(const void* p) {
    return (uint32_t)__cvta_generic_to_shared(p);
}
#define CP16(d, s) asm volatile("cp.async.cg.shared.global [%0], [%1], 16;" :: "r"(d), "l"(s))
#define CP_COMMIT  asm volatile("cp.async.commit_group;" ::: "memory")
#define CP_WAIT1   asm volatile("cp.async.wait_group 1;" ::: "memory")
#define CP_WAIT0   asm volatile("cp.async.wait_group 0;" ::: "memory")

// ------------------------- prep kernels -------------------------
__global__ void zero_flag() { g_mask_any = 0; }
__global__ __launch_bounds__(256) void mask_scan(const uint4* __restrict__ m, int n4)
{
    uint32_t acc = 0;
    for (int i = blockIdx.x * 256 + threadIdx.x; i < n4; i += gridDim.x * 256) {
        uint4 v = m[i];
        acc |= v.x | v.y | v.z | v.w;
    }
    acc |= __shfl_xor_sync(0xffffffff, acc, 16);
    acc |= __shfl_xor_sync(0xffffffff, acc, 8);
    acc |= __shfl_xor_sync(0xffffffff, acc, 4);
    acc |= __shfl_xor_sync(0xffffffff, acc, 2);
    acc |= __shfl_xor_sync(0xffffffff, acc, 1);
    if ((threadIdx.x & 31) == 0 && acc) atomicOr(&g_mask_any, 1);
}

__global__ __launch_bounds__(256) void pack_all(
    const float* q, const float* k, const float* v,
    const float* Wq, const float* Wk, const float* Wv, const float* Wo)
{
    const size_t NI = 4096 * 512, NW = 1024 * 512;
    size_t gid = (size_t)blockIdx.x * 256 + threadIdx.x;
    const size_t stride = (size_t)gridDim.x * 256;
    const size_t total = 3 * NI + 4 * NW;
    for (size_t i = gid; i < total; i += stride) {
        const float* src; uint32_t *dh, *dl; size_t off;
        if (i < NI)            { src = q;  dh = g_qh;  dl = g_ql;  off = i; }
        else if (i < 2*NI)     { src = k;  dh = g_kh;  dl = g_kl;  off = i - NI; }
        else if (i < 3*NI)     { src = v;  dh = g_vh;  dl = g_vl;  off = i - 2*NI; }
        else if (i < 3*NI+NW)  { src = Wq; dh = g_Wqh; dl = g_Wql; off = i - 3*NI; }
        else if (i < 3*NI+2*NW){ src = Wk; dh = g_Wkh; dl = g_Wkl; off = i - 3*NI - NW; }
        else if (i < 3*NI+3*NW){ src = Wv; dh = g_Wvh; dl = g_Wvl; off = i - 3*NI - 2*NW; }
        else                   { src = Wo; dh = g_Woh; dl = g_Wol; off = i - 3*NI - 3*NW; }
        float2 vv = ((const float2*)src)[off];
        uint32_t h, l; split2(vv.x, vv.y, h, l);
        dh[off] = h; dl[off] = l;
    }
}

__global__ __launch_bounds__(128) void v_pack()
{
    __shared__ float tile[64][65];
    const int tid = threadIdx.x;
    const int bh = blockIdx.y, kt = blockIdx.x * 64;
    const float* Vb = g_V + ((size_t)bh * 2048 + kt) * 64;
#pragma unroll
    for (int i = 0; i < 16; i++) {
        int idx = tid + i * 128;
        int r = idx >> 5, dp = idx & 31;
        float2 v = ((const float2*)Vb)[r * 32 + dp];
        tile[r][dp * 2] = v.x; tile[r][dp * 2 + 1] = v.y;
    }
    __syncthreads();
#pragma unroll
    for (int i = 0; i < 16; i++) {
        int idx = tid + i * 128;
        int d = idx >> 5, kp = idx & 31;
        uint32_t h, l; split2(tile[2 * kp][d], tile[2 * kp + 1][d], h, l);
        size_t o = ((size_t)bh * 64 + d) * 1024 + (kt >> 1) + kp;
        g_Vh[o] = h; g_Vl[o] = l;
    }
}

// ------------------------- GEMM mainloop: hi/lo planes + ldmatrix -------------------------
#define GSTR 20                    // words per 16-word row (bank-cycling pad)
#define PLW  (128 * GSTR)          // words per plane
#define STW  (4 * PLW)             // words per stage (AH AL BH BL)

__device__ __forceinline__ void gemm_mainloop_pl(
    const uint32_t* __restrict__ Ah, const uint32_t* __restrict__ Al,
    const uint32_t* __restrict__ Bh, const uint32_t* __restrict__ Bl,
    int bm, int bn, uint32_t* sm, float acc[4][4][4],
    int wm, int wn, int lane, int tid)
{
    const uint32_t* gAh = Ah + (size_t)bm * 512;
    const uint32_t* gAl = Al + (size_t)bm * 512;
    const uint32_t* gBh = Bh + (size_t)bn * 512;
    const uint32_t* gBl = Bl + (size_t)bn * 512;
    const int pr = tid >> 2, pj = (tid & 3) * 4;   // producer: rows pr, pr+64; 16B chunk pj

#define GISSUE(it_) do { \
    uint32_t* st_ = sm + ((it_) & 1) * STW; \
    _Pragma("unroll") \
    for (int u_ = 0; u_ < 2; u_++) { \
        const int row_ = pr + u_ * 64; \
        const size_t go_ = (size_t)row_ * 512 + (it_) * 16 + pj; \
        const int so_ = row_ * GSTR + pj; \
        CP16(s2u(&st_[so_]),            &gAh[go_]); \
        CP16(s2u(&st_[PLW + so_]),      &gAl[go_]); \
        CP16(s2u(&st_[2*PLW + so_]),    &gBh[go_]); \
        CP16(s2u(&st_[3*PLW + so_]),    &gBl[go_]); \
    } } while(0)

    const uint32_t smb = s2u(sm);
    const int lrow = (lane & 7) + ((lane >> 3) & 1) * 8;
    const int lseg = (lane >> 4) * 16;

    GISSUE(0); CP_COMMIT;
    for (int it = 0; it < 32; ++it) {
        if (it < 31) { GISSUE(it + 1); CP_COMMIT; CP_WAIT1; }
        else CP_WAIT0;
        __syncthreads();
        const uint32_t stb = smb + ((it & 1) * STW) * 4;
#pragma unroll
        for (int c = 0; c < 2; ++c) {
            uint32_t ah[4][4], al[4][4];
#pragma unroll
            for (int mt = 0; mt < 4; ++mt) {
                uint32_t ra = stb + (uint32_t)((wm + mt * 16 + lrow) * GSTR) * 4 + c * 32 + lseg;
                ldx4(ah[mt], ra);
                ldx4(al[mt], ra + PLW * 4);
            }
#pragma unroll
            for (int p = 0; p < 2; ++p) {
                uint32_t bbh[4], bbl[4];
                uint32_t rb = stb + (uint32_t)(2 * PLW) * 4
                            + (uint32_t)((wn + p * 16 + lrow) * GSTR) * 4 + c * 32 + lseg;
                ldx4(bbh, rb);
                ldx4(bbl, rb + PLW * 4);
#pragma unroll
                for (int mt = 0; mt < 4; ++mt) {
                    mma_bf16(acc[mt][2*p],   ah[mt], bbh[0], bbh[2]);
                    mma_bf16(acc[mt][2*p],   ah[mt], bbl[0], bbl[2]);
                    mma_bf16(acc[mt][2*p],   al[mt], bbh[0], bbh[2]);
                    mma_bf16(acc[mt][2*p+1], ah[mt], bbh[1], bbh[3]);
                    mma_bf16(acc[mt][2*p+1], ah[mt], bbl[1], bbl[3]);
                    mma_bf16(acc[mt][2*p+1], al[mt], bbh[1], bbh[3]);
                }
            }
        }
        __syncthreads();
    }
#undef GISSUE
}

// ------------------------- fused QKV projection -------------------------
#define QSCALE 0.18033688f   // (1/8) * log2(e)
__global__ __launch_bounds__(256, 2) void gemm_qkv()
{
    extern __shared__ __align__(16) uint32_t smw[];
    const int which = blockIdx.x >> 3;
    const int bn = (blockIdx.x & 7) * 128;
    const int bm = blockIdx.y * 128;

    const uint32_t* Ah = which == 0 ? g_qh : which == 1 ? g_kh : g_vh;
    const uint32_t* Al = which == 0 ? g_ql : which == 1 ? g_kl : g_vl;
    const uint32_t* Bh = which == 0 ? g_Wqh : which == 1 ? g_Wkh : g_Wvh;
    const uint32_t* Bl = which == 0 ? g_Wql : which == 1 ? g_Wkl : g_Wvl;

    const int tid = threadIdx.x;
    const int wid = tid >> 5, lane = tid & 31;
    const int wm = (wid & 1) * 64, wn = (wid >> 1) * 32;
    const int lr = lane >> 2, lc = lane & 3;

    float acc[4][4][4];
#pragma unroll
    for (int mt = 0; mt < 4; mt++)
#pragma unroll
        for (int nt = 0; nt < 4; nt++)
#pragma unroll
            for (int i = 0; i < 4; i++) acc[mt][nt][i] = 0.f;

    gemm_mainloop_pl(Ah, Al, Bh, Bl, bm, bn, smw, acc, wm, wn, lane, tid);

    if (which == 0) {
#pragma unroll
        for (int mt = 0; mt < 4; ++mt)
#pragma unroll
            for (int nt = 0; nt < 4; ++nt) {
                const int row  = bm + wm + mt * 16 + lr;
                const int col0 = bn + wn + nt * 8 + lc * 2;
                const int hh = col0 >> 6, j = (col0 & 63) >> 1;
                const float* d = acc[mt][nt];
                uint32_t h, l;
                int b = row >> 11, t = row & 2047;
                split2(d[0] * QSCALE, d[1] * QSCALE, h, l);
                g_Qpk[((size_t)(b * 16 + hh) * 2048 + t) * 32 + j] = make_uint2(h, l);
                b = (row + 8) >> 11; t = (row + 8) & 2047;
                split2(d[2] * QSCALE, d[3] * QSCALE, h, l);
                g_Qpk[((size_t)(b * 16 + hh) * 2048 + t) * 32 + j] = make_uint2(h, l);
            }
    } else if (which == 1) {
#pragma unroll
        for (int mt = 0; mt < 4; ++mt)
#pragma unroll
            for (int nt = 0; nt < 4; ++nt) {
                const int row  = bm + wm + mt * 16 + lr;
                const int col0 = bn + wn + nt * 8 + lc * 2;
                const int hh = col0 >> 6, j = (col0 & 63) >> 1;
                const float* d = acc[mt][nt];
                uint32_t h, l;
                int b = row >> 11, t = row & 2047;
                size_t o = ((size_t)(b * 16 + hh) * 2048 + t) * 32 + j;
                split2(d[0], d[1], h, l);
                g_Kh[o] = h; g_Kl[o] = l;
                b = (row + 8) >> 11; t = (row + 8) & 2047;
                o = ((size_t)(b * 16 + hh) * 2048 + t) * 32 + j;
                split2(d[2], d[3], h, l);
                g_Kh[o] = h; g_Kl[o] = l;
            }
    } else {
#pragma unroll
        for (int mt = 0; mt < 4; ++mt)
#pragma unroll
            for (int nt = 0; nt < 4; ++nt) {
                const int row  = bm + wm + mt * 16 + lr;
                const int col0 = bn + wn + nt * 8 + lc * 2;
                const int hh = col0 >> 6, dd = col0 & 63;
                const float* d = acc[mt][nt];
                int b = row >> 11, t = row & 2047;
                *(float2*)(g_V + (((size_t)(b * 16 + hh) * 2048 + t) * 64 + dd)) = make_float2(d[0], d[1]);
                b = (row + 8) >> 11; t = (row + 8) & 2047;
                *(float2*)(g_V + (((size_t)(b * 16 + hh) * 2048 + t) * 64 + dd)) = make_float2(d[2], d[3]);
            }
    }
}

// ------------------------- output projection -------------------------
__global__ __launch_bounds__(256, 2) void gemm_oproj(float* __restrict__ C)
{
    extern __shared__ __align__(16) uint32_t smw[];
    const int bn = blockIdx.x * 128;
    const int bm = blockIdx.y * 128;
    const int tid = threadIdx.x;
    const int wid = tid >> 5, lane = tid & 31;
    const int wm = (wid & 1) * 64, wn = (wid >> 1) * 32;
    const int lr = lane >> 2, lc = lane & 3;

    float acc[4][4][4];
#pragma unroll
    for (int mt = 0; mt < 4; mt++)
#pragma unroll
        for (int nt = 0; nt < 4; nt++)
#pragma unroll
            for (int i = 0; i < 4; i++) acc[mt][nt][i] = 0.f;

    gemm_mainloop_pl(g_Ah, g_Al, g_Woh, g_Wol, bm, bn, smw, acc, wm, wn, lane, tid);

#pragma unroll
    for (int mt = 0; mt < 4; ++mt)
#pragma unroll
        for (int nt = 0; nt < 4; ++nt) {
            const int row  = bm + wm + mt * 16 + lr;
            const int col0 = bn + wn + nt * 8 + lc * 2;
            const float* d = acc[mt][nt];
            *(float2*)(C + (size_t)row * 1024 + col0)       = make_float2(d[0], d[1]);
            *(float2*)(C + (size_t)(row + 8) * 1024 + col0) = make_float2(d[2], d[3]);
        }
}

// ------------------------- flash attention: planes + ldmatrix + ex2 -------------------------
#define KSTR 36    // words per 32-word row
__global__ __launch_bounds__(128, 4) void flash_attn6(
    const unsigned char* __restrict__ mask)
{
    __shared__ __align__(16) uint32_t SKh[64*KSTR], SKl[64*KSTR], SVh[64*KSTR], SVl[64*KSTR];

    const int tid = threadIdx.x;
    const int w = tid >> 5, lane = tid & 31;
    const int lr = lane >> 2, lc = lane & 3;
    const int bh = blockIdx.y, b = bh >> 4, h = bh & 15;
    const int q0 = blockIdx.x * 64;
    const int t0 = q0 + w * 16;
    const bool anymask = (g_mask_any != 0);

    uint32_t qh[4][4], ql[4][4];
    {
        const uint2* q0p = g_Qpk + ((size_t)bh * 2048 + t0 + lr) * 32;
        const uint2* q1p = q0p + 8 * 32;
#pragma unroll
        for (int c = 0; c < 4; c++) {
            const int j = c * 8 + lc;
            uint2 u;
            u = q0p[j];     qh[c][0] = u.x; ql[c][0] = u.y;
            u = q1p[j];     qh[c][1] = u.x; ql[c][1] = u.y;
            u = q0p[j + 4]; qh[c][2] = u.x; ql[c][2] = u.y;
            u = q1p[j + 4]; qh[c][3] = u.x; ql[c][3] = u.y;
        }
    }

    float m0 = -1e30f, m1 = -1e30f, l0 = 0.f, l1 = 0.f;
    float o[8][4];
#pragma unroll
    for (int nt = 0; nt < 8; nt++)
#pragma unroll
        for (int i = 0; i < 4; i++) o[nt][i] = 0.f;

    const unsigned char* mrow0 = mask + ((size_t)b * 2048 + t0 + lr) * 2048;
    const unsigned char* mrow1 = mrow0 + 8 * 2048;

    const uint32_t skh = s2u(SKh), skl = s2u(SKl), svh = s2u(SVh), svl = s2u(SVl);
    const int lrow = (lane & 7) + ((lane >> 3) & 1) * 8;
    const int lseg = (lane >> 4) * 16;

    // producer mapping: 512 chunks16B per plane, 4 per thread: r = idx>>3, j4 = (idx&7)*4
    for (int kt = 0; kt < 2048; kt += 64) {
        __syncthreads();
        {
            const uint32_t* KH = g_Kh + ((size_t)bh * 2048 + kt) * 32;
            const uint32_t* KL = g_Kl + ((size_t)bh * 2048 + kt) * 32;
            const uint32_t* VH = g_Vh + (size_t)bh * 64 * 1024 + (kt >> 1);
            const uint32_t* VL = g_Vl + (size_t)bh * 64 * 1024 + (kt >> 1);
#pragma unroll
            for (int i = 0; i < 4; i++) {
                int idx = tid + i * 128;
                int r = idx >> 3, j4 = (idx & 7) * 4;
                *(uint4*)&SKh[r * KSTR + j4] = *(const uint4*)&KH[r * 32 + j4];
                *(uint4*)&SKl[r * KSTR + j4] = *(const uint4*)&KL[r * 32 + j4];
                *(uint4*)&SVh[r * KSTR + j4] = *(const uint4*)&VH[(size_t)r * 1024 + j4];
                *(uint4*)&SVl[r * KSTR + j4] = *(const uint4*)&VL[(size_t)r * 1024 + j4];
            }
        }
        __syncthreads();

        // S = Q K^T
        float s[8][4];
#pragma unroll
        for (int nt = 0; nt < 8; nt++)
#pragma unroll
            for (int i = 0; i < 4; i++) s[nt][i] = 0.f;
#pragma unroll
        for (int c = 0; c < 4; c++) {
#pragma unroll
            for (int p = 0; p < 4; p++) {
                uint32_t kbh[4], kbl[4];
                uint32_t ra = (uint32_t)((p * 16 + lrow) * KSTR) * 4 + c * 32 + lseg;
                ldx4(kbh, skh + ra);
                ldx4(kbl, skl + ra);
                mma_bf16(s[2*p],   qh[c], kbh[0], kbh[2]);
                mma_bf16(s[2*p],   qh[c], kbl[0], kbl[2]);
                mma_bf16(s[2*p],   ql[c], kbh[0], kbh[2]);
                mma_bf16(s[2*p+1], qh[c], kbh[1], kbh[3]);
                mma_bf16(s[2*p+1], qh[c], kbl[1], kbl[3]);
                mma_bf16(s[2*p+1], ql[c], kbh[1], kbh[3]);
            }
        }

        if (anymask) {
#pragma unroll
            for (int nt = 0; nt < 8; nt++) {
                const int cc = kt + nt * 8 + lc * 2;
                if (mrow0[cc])     s[nt][0] = -1e30f;
                if (mrow0[cc + 1]) s[nt][1] = -1e30f;
                if (mrow1[cc])     s[nt][2] = -1e30f;
                if (mrow1[cc + 1]) s[nt][3] = -1e30f;
            }
        }

        // online softmax (base-2 logits; log2e folded into Q scale)
        float tm0 = -1e30f, tm1 = -1e30f;
#pragma unroll
        for (int nt = 0; nt < 8; nt++) {
            tm0 = fmaxf(tm0, fmaxf(s[nt][0], s[nt][1]));
            tm1 = fmaxf(tm1, fmaxf(s[nt][2], s[nt][3]));
        }
        tm0 = fmaxf(tm0, __shfl_xor_sync(0xffffffff, tm0, 1));
        tm0 = fmaxf(tm0, __shfl_xor_sync(0xffffffff, tm0, 2));
        tm1 = fmaxf(tm1, __shfl_xor_sync(0xffffffff, tm1, 1));
        tm1 = fmaxf(tm1, __shfl_xor_sync(0xffffffff, tm1, 2));
        float mn0 = fmaxf(m0, tm0), mn1 = fmaxf(m1, tm1);
        float cr0 = ex2(m0 - mn0), cr1 = ex2(m1 - mn1);
        m0 = mn0; m1 = mn1;
        float ts0 = 0.f, ts1 = 0.f;
#pragma unroll
        for (int nt = 0; nt < 8; nt++) {
            s[nt][0] = ex2(s[nt][0] - mn0);
            s[nt][1] = ex2(s[nt][1] - mn0);
            s[nt][2] = ex2(s[nt][2] - mn1);
            s[nt][3] = ex2(s[nt][3] - mn1);
            ts0 += s[nt][0] + s[nt][1];
            ts1 += s[nt][2] + s[nt][3];
        }
        ts0 += __shfl_xor_sync(0xffffffff, ts0, 1);
        ts0 += __shfl_xor_sync(0xffffffff, ts0, 2);
        ts1 += __shfl_xor_sync(0xffffffff, ts1, 1);
        ts1 += __shfl_xor_sync(0xffffffff, ts1, 2);
        l0 = l0 * cr0 + ts0;
        l1 = l1 * cr1 + ts1;
#pragma unroll
        for (int nt = 0; nt < 8; nt++) {
            o[nt][0] *= cr0; o[nt][1] *= cr0;
            o[nt][2] *= cr1; o[nt][3] *= cr1;
        }

        // PV
#pragma unroll
        for (int kc = 0; kc < 4; kc++) {
            uint32_t ph[4], pl[4];
            split2(s[2*kc][0],   s[2*kc][1],   ph[0], pl[0]);
            split2(s[2*kc][2],   s[2*kc][3],   ph[1], pl[1]);
            split2(s[2*kc+1][0], s[2*kc+1][1], ph[2], pl[2]);
            split2(s[2*kc+1][2], s[2*kc+1][3], ph[3], pl[3]);
#pragma unroll
            for (int p = 0; p < 4; p++) {
                uint32_t vbh[4], vbl[4];
                uint32_t ra = (uint32_t)((p * 16 + lrow) * KSTR) * 4 + kc * 32 + lseg;
                ldx4(vbh, svh + ra);
                ldx4(vbl, svl + ra);
                mma_bf16(o[2*p],   ph, vbh[0], vbh[2]);
                mma_bf16(o[2*p],   ph, vbl[0], vbl[2]);
                mma_bf16(o[2*p],   pl, vbh[0], vbh[2]);
                mma_bf16(o[2*p+1], ph, vbh[1], vbh[3]);
                mma_bf16(o[2*p+1], ph, vbl[1], vbl[3]);
                mma_bf16(o[2*p+1], pl, vbh[1], vbh[3]);
            }
        }
    }

    const float inv0 = 1.f / l0, inv1 = 1.f / l1;
    uint32_t* A0h = g_Ah + ((size_t)b * 2048 + t0 + lr) * 512 + h * 32;
    uint32_t* A0l = g_Al + ((size_t)b * 2048 + t0 + lr) * 512 + h * 32;
#pragma unroll
    for (int nt = 0; nt < 8; nt++) {
        const int j = nt * 4 + lc;
        uint32_t hh, ll;
        split2(o[nt][0] * inv0, o[nt][1] * inv0, hh, ll);
        A0h[j] = hh; A0l[j] = ll;
        split2(o[nt][2] * inv1, o[nt][3] * inv1, hh, ll);
        A0h[8 * 512 + j] = hh; A0l[8 * 512 + j] = ll;
    }
}

extern "C" void kernel_launch(void* const* d_in, const int* in_sizes, int n_in,
                              void* d_out, int out_size)
{
    const float* query = (const float*)d_in[0];
    const float* key   = (const float*)d_in[1];
    const float* value = (const float*)d_in[2];
    const unsigned char* mask = (const unsigned char*)d_in[3];
    const float* Wq = (const float*)d_in[4];
    const float* Wk = (const float*)d_in[5];
    const float* Wv = (const float*)d_in[6];
    const float* Wo = (const float*)d_in[7];

    const int SMEM_GEMM = 2 * STW * 4;   // 81920 B
    cudaFuncSetAttribute(gemm_qkv,   cudaFuncAttributeMaxDynamicSharedMemorySize, SMEM_GEMM);
    cudaFuncSetAttribute(gemm_oproj, cudaFuncAttributeMaxDynamicSharedMemorySize, SMEM_GEMM);

    zero_flag<<<1, 1>>>();
    mask_scan<<<256, 256>>>((const uint4*)mask, (B_ * T_ * T_) / 16);

    pack_all<<<2048, 256>>>(query, key, value, Wq, Wk, Wv, Wo);

    dim3 gq(24, 32);
    gemm_qkv<<<gq, 256, SMEM_GEMM>>>();

    dim3 gv(32, 32);
    v_pack<<<gv, 128>>>();

    dim3 ga(T_ / 64, B_ * H_);
    flash_attn6<<<ga, 128>>>(mask);

    dim3 go(8, 32);
    gemm_oproj<<<go, 256, SMEM_GEMM>>>((float*)d_out);
}

// round 10
// speedup vs baseline: 1.2742x; 1.0005x over previous
#include <cuda_runtime.h>
#include <cstdint>
#include <math.h>

#define B_  2
#define T_  2048
#define D_  1024
#define H_  16
#define DH  64

// ------------------------- scratch: hi/lo plane globals -------------------------
__device__ uint32_t g_qh[4096*512], g_ql[4096*512];
__device__ uint32_t g_kh[4096*512], g_kl[4096*512];
__device__ uint32_t g_vh[4096*512], g_vl[4096*512];
__device__ uint32_t g_Wqh[1024*512], g_Wql[1024*512];
__device__ uint32_t g_Wkh[1024*512], g_Wkl[1024*512];
__device__ uint32_t g_Wvh[1024*512], g_Wvl[1024*512];
__device__ uint32_t g_Woh[1024*512], g_Wol[1024*512];
__device__ uint2    g_Qpk[B_*H_*T_*32];
__device__ uint32_t g_Kh[B_*H_*T_*32], g_Kl[B_*H_*T_*32];
__device__ float    g_V [B_*H_*T_*DH];
__device__ uint32_t g_Vh[(size_t)B_*H_*DH*1024], g_Vl[(size_t)B_*H_*DH*1024];
__device__ uint32_t g_Ah[(size_t)4096*512], g_Al[(size_t)4096*512];
__device__ int      g_mask_any;

// ------------------------- helpers -------------------------
__device__ __forceinline__ uint32_t packbf(float x, float y) {
    uint32_t r; asm("cvt.rn.bf16x2.f32 %0, %1, %2;" : "=r"(r) : "f"(y), "f"(x)); return r;
}
__device__ __forceinline__ void split2(float x, float y, uint32_t& h, uint32_t& l) {
    h = packbf(x, y);
    float hx = __uint_as_float(h << 16);
    float hy = __uint_as_float(h & 0xFFFF0000u);
    l = packbf(x - hx, y - hy);
}
__device__ __forceinline__ void mma_bf16(float* d, const uint32_t* a, uint32_t b0, uint32_t b1) {
    asm volatile("mma.sync.aligned.m16n8k16.row.col.f32.bf16.bf16.f32 "
        "{%0,%1,%2,%3}, {%4,%5,%6,%7}, {%8,%9}, {%0,%1,%2,%3};"
        : "+f"(d[0]), "+f"(d[1]), "+f"(d[2]), "+f"(d[3])
        : "r"(a[0]), "r"(a[1]), "r"(a[2]), "r"(a[3]), "r"(b0), "r"(b1));
}
__device__ __forceinline__ void ldx4(uint32_t* r, uint32_t addr) {
    asm volatile("ldmatrix.sync.aligned.m8n8.x4.shared.b16 {%0,%1,%2,%3}, [%4];"
        : "=r"(r[0]), "=r"(r[1]), "=r"(r[2]), "=r"(r[3]) : "r"(addr));
}
__device__ __forceinline__ float ex2(float x) {
    float y; asm("ex2.approx.f32 %0, %1;" : "=f"(y) : "f"(x)); return y;
}
__device__ __forceinline__ uint32_t s2u(const void* p) {
    return (uint32_t)__cvta_generic_to_shared(p);
}
#define CP16(d, s) asm volatile("cp.async.cg.shared.global [%0], [%1], 16;" :: "r"(d), "l"(s))
#define CP_COMMIT  asm volatile("cp.async.commit_group;" ::: "memory")
#define CP_WAIT1   asm volatile("cp.async.wait_group 1;" ::: "memory")
#define CP_WAIT0   asm volatile("cp.async.wait_group 0;" ::: "memory")

// ------------------------- prep kernels -------------------------
__global__ void zero_flag() { g_mask_any = 0; }
__global__ __launch_bounds__(256) void mask_scan(const uint4* __restrict__ m, int n4)
{
    uint32_t acc = 0;
    for (int i = blockIdx.x * 256 + threadIdx.x; i < n4; i += gridDim.x * 256) {
        uint4 v = m[i];
        acc |= v.x | v.y | v.z | v.w;
    }
    acc |= __shfl_xor_sync(0xffffffff, acc, 16);
    acc |= __shfl_xor_sync(0xffffffff, acc, 8);
    acc |= __shfl_xor_sync(0xffffffff, acc, 4);
    acc |= __shfl_xor_sync(0xffffffff, acc, 2);
    acc |= __shfl_xor_sync(0xffffffff, acc, 1);
    if ((threadIdx.x & 31) == 0 && acc) atomicOr(&g_mask_any, 1);
}

__global__ __launch_bounds__(256) void pack_all(
    const float* q, const float* k, const float* v,
    const float* Wq, const float* Wk, const float* Wv, const float* Wo)
{
    const size_t NI = 4096 * 512, NW = 1024 * 512;
    size_t gid = (size_t)blockIdx.x * 256 + threadIdx.x;
    const size_t stride = (size_t)gridDim.x * 256;
    const size_t total = 3 * NI + 4 * NW;
    for (size_t i = gid; i < total; i += stride) {
        const float* src; uint32_t *dh, *dl; size_t off;
        if (i < NI)            { src = q;  dh = g_qh;  dl = g_ql;  off = i; }
        else if (i < 2*NI)     { src = k;  dh = g_kh;  dl = g_kl;  off = i - NI; }
        else if (i < 3*NI)     { src = v;  dh = g_vh;  dl = g_vl;  off = i - 2*NI; }
        else if (i < 3*NI+NW)  { src = Wq; dh = g_Wqh; dl = g_Wql; off = i - 3*NI; }
        else if (i < 3*NI+2*NW){ src = Wk; dh = g_Wkh; dl = g_Wkl; off = i - 3*NI - NW; }
        else if (i < 3*NI+3*NW){ src = Wv; dh = g_Wvh; dl = g_Wvl; off = i - 3*NI - 2*NW; }
        else                   { src = Wo; dh = g_Woh; dl = g_Wol; off = i - 3*NI - 3*NW; }
        float2 vv = ((const float2*)src)[off];
        uint32_t h, l; split2(vv.x, vv.y, h, l);
        dh[off] = h; dl[off] = l;
    }
}

__global__ __launch_bounds__(128) void v_pack()
{
    __shared__ float tile[64][65];
    const int tid = threadIdx.x;
    const int bh = blockIdx.y, kt = blockIdx.x * 64;
    const float* Vb = g_V + ((size_t)bh * 2048 + kt) * 64;
#pragma unroll
    for (int i = 0; i < 16; i++) {
        int idx = tid + i * 128;
        int r = idx >> 5, dp = idx & 31;
        float2 v = ((const float2*)Vb)[r * 32 + dp];
        tile[r][dp * 2] = v.x; tile[r][dp * 2 + 1] = v.y;
    }
    __syncthreads();
#pragma unroll
    for (int i = 0; i < 16; i++) {
        int idx = tid + i * 128;
        int d = idx >> 5, kp = idx & 31;
        uint32_t h, l; split2(tile[2 * kp][d], tile[2 * kp + 1][d], h, l);
        size_t o = ((size_t)bh * 64 + d) * 1024 + (kt >> 1) + kp;
        g_Vh[o] = h; g_Vl[o] = l;
    }
}

// ------------------------- GEMM mainloop: reordered mma issue -------------------------
#define GSTR 20
#define PLW  (128 * GSTR)
#define STW  (4 * PLW)

__device__ __forceinline__ void gemm_mainloop_pl(
    const uint32_t* __restrict__ Ah, const uint32_t* __restrict__ Al,
    const uint32_t* __restrict__ Bh, const uint32_t* __restrict__ Bl,
    int bm, int bn, uint32_t* sm, float acc[4][4][4],
    int wm, int wn, int lane, int tid)
{
    const uint32_t* gAh = Ah + (size_t)bm * 512;
    const uint32_t* gAl = Al + (size_t)bm * 512;
    const uint32_t* gBh = Bh + (size_t)bn * 512;
    const uint32_t* gBl = Bl + (size_t)bn * 512;
    const int pr = tid >> 2, pj = (tid & 3) * 4;

#define GISSUE(it_) do { \
    uint32_t* st_ = sm + ((it_) & 1) * STW; \
    _Pragma("unroll") \
    for (int u_ = 0; u_ < 2; u_++) { \
        const int row_ = pr + u_ * 64; \
        const size_t go_ = (size_t)row_ * 512 + (it_) * 16 + pj; \
        const int so_ = row_ * GSTR + pj; \
        CP16(s2u(&st_[so_]),            &gAh[go_]); \
        CP16(s2u(&st_[PLW + so_]),      &gAl[go_]); \
        CP16(s2u(&st_[2*PLW + so_]),    &gBh[go_]); \
        CP16(s2u(&st_[3*PLW + so_]),    &gBl[go_]); \
    } } while(0)

    const uint32_t smb = s2u(sm);
    const int lrow = (lane & 7) + ((lane >> 3) & 1) * 8;
    const int lseg = (lane >> 4) * 16;

    GISSUE(0); CP_COMMIT;
    for (int it = 0; it < 32; ++it) {
        if (it < 31) { GISSUE(it + 1); CP_COMMIT; CP_WAIT1; }
        else CP_WAIT0;
        __syncthreads();
        const uint32_t stb = smb + ((it & 1) * STW) * 4;
#pragma unroll
        for (int c = 0; c < 2; ++c) {
            uint32_t ah[4][4], al[4][4];
#pragma unroll
            for (int mt = 0; mt < 4; ++mt) {
                uint32_t ra = stb + (uint32_t)((wm + mt * 16 + lrow) * GSTR) * 4 + c * 32 + lseg;
                ldx4(ah[mt], ra);
                ldx4(al[mt], ra + PLW * 4);
            }
#pragma unroll
            for (int p = 0; p < 2; ++p) {
                uint32_t bbh[4], bbl[4];
                uint32_t rb = stb + (uint32_t)(2 * PLW) * 4
                            + (uint32_t)((wn + p * 16 + lrow) * GSTR) * 4 + c * 32 + lseg;
                ldx4(bbh, rb);
                ldx4(bbl, rb + PLW * 4);
                // term-major: dependent mmas 8 apart
#pragma unroll
                for (int mt = 0; mt < 4; ++mt) {
                    mma_bf16(acc[mt][2*p],   ah[mt], bbh[0], bbh[2]);
                    mma_bf16(acc[mt][2*p+1], ah[mt], bbh[1], bbh[3]);
                }
#pragma unroll
                for (int mt = 0; mt < 4; ++mt) {
                    mma_bf16(acc[mt][2*p],   ah[mt], bbl[0], bbl[2]);
                    mma_bf16(acc[mt][2*p+1], ah[mt], bbl[1], bbl[3]);
                }
#pragma unroll
                for (int mt = 0; mt < 4; ++mt) {
                    mma_bf16(acc[mt][2*p],   al[mt], bbh[0], bbh[2]);
                    mma_bf16(acc[mt][2*p+1], al[mt], bbh[1], bbh[3]);
                }
            }
        }
        __syncthreads();
    }
#undef GISSUE
}

// ------------------------- fused QKV projection -------------------------
#define QSCALE 0.18033688f   // (1/8) * log2(e)
__global__ __launch_bounds__(256, 2) void gemm_qkv()
{
    extern __shared__ __align__(16) uint32_t smw[];
    const int which = blockIdx.x >> 3;
    const int bn = (blockIdx.x & 7) * 128;
    const int bm = blockIdx.y * 128;

    const uint32_t* Ah = which == 0 ? g_qh : which == 1 ? g_kh : g_vh;
    const uint32_t* Al = which == 0 ? g_ql : which == 1 ? g_kl : g_vl;
    const uint32_t* Bh = which == 0 ? g_Wqh : which == 1 ? g_Wkh : g_Wvh;
    const uint32_t* Bl = which == 0 ? g_Wql : which == 1 ? g_Wkl : g_Wvl;

    const int tid = threadIdx.x;
    const int wid = tid >> 5, lane = tid & 31;
    const int wm = (wid & 1) * 64, wn = (wid >> 1) * 32;
    const int lr = lane >> 2, lc = lane & 3;

    float acc[4][4][4];
#pragma unroll
    for (int mt = 0; mt < 4; mt++)
#pragma unroll
        for (int nt = 0; nt < 4; nt++)
#pragma unroll
            for (int i = 0; i < 4; i++) acc[mt][nt][i] = 0.f;

    gemm_mainloop_pl(Ah, Al, Bh, Bl, bm, bn, smw, acc, wm, wn, lane, tid);

    if (which == 0) {
#pragma unroll
        for (int mt = 0; mt < 4; ++mt)
#pragma unroll
            for (int nt = 0; nt < 4; ++nt) {
                const int row  = bm + wm + mt * 16 + lr;
                const int col0 = bn + wn + nt * 8 + lc * 2;
                const int hh = col0 >> 6, j = (col0 & 63) >> 1;
                const float* d = acc[mt][nt];
                uint32_t h, l;
                int b = row >> 11, t = row & 2047;
                split2(d[0] * QSCALE, d[1] * QSCALE, h, l);
                g_Qpk[((size_t)(b * 16 + hh) * 2048 + t) * 32 + j] = make_uint2(h, l);
                b = (row + 8) >> 11; t = (row + 8) & 2047;
                split2(d[2] * QSCALE, d[3] * QSCALE, h, l);
                g_Qpk[((size_t)(b * 16 + hh) * 2048 + t) * 32 + j] = make_uint2(h, l);
            }
    } else if (which == 1) {
#pragma unroll
        for (int mt = 0; mt < 4; ++mt)
#pragma unroll
            for (int nt = 0; nt < 4; ++nt) {
                const int row  = bm + wm + mt * 16 + lr;
                const int col0 = bn + wn + nt * 8 + lc * 2;
                const int hh = col0 >> 6, j = (col0 & 63) >> 1;
                const float* d = acc[mt][nt];
                uint32_t h, l;
                int b = row >> 11, t = row & 2047;
                size_t o = ((size_t)(b * 16 + hh) * 2048 + t) * 32 + j;
                split2(d[0], d[1], h, l);
                g_Kh[o] = h; g_Kl[o] = l;
                b = (row + 8) >> 11; t = (row + 8) & 2047;
                o = ((size_t)(b * 16 + hh) * 2048 + t) * 32 + j;
                split2(d[2], d[3], h, l);
                g_Kh[o] = h; g_Kl[o] = l;
            }
    } else {
#pragma unroll
        for (int mt = 0; mt < 4; ++mt)
#pragma unroll
            for (int nt = 0; nt < 4; ++nt) {
                const int row  = bm + wm + mt * 16 + lr;
                const int col0 = bn + wn + nt * 8 + lc * 2;
                const int hh = col0 >> 6, dd = col0 & 63;
                const float* d = acc[mt][nt];
                int b = row >> 11, t = row & 2047;
                *(float2*)(g_V + (((size_t)(b * 16 + hh) * 2048 + t) * 64 + dd)) = make_float2(d[0], d[1]);
                b = (row + 8) >> 11; t = (row + 8) & 2047;
                *(float2*)(g_V + (((size_t)(b * 16 + hh) * 2048 + t) * 64 + dd)) = make_float2(d[2], d[3]);
            }
    }
}

// ------------------------- output projection -------------------------
__global__ __launch_bounds__(256, 2) void gemm_oproj(float* __restrict__ C)
{
    extern __shared__ __align__(16) uint32_t smw[];
    const int bn = blockIdx.x * 128;
    const int bm = blockIdx.y * 128;
    const int tid = threadIdx.x;
    const int wid = tid >> 5, lane = tid & 31;
    const int wm = (wid & 1) * 64, wn = (wid >> 1) * 32;
    const int lr = lane >> 2, lc = lane & 3;

    float acc[4][4][4];
#pragma unroll
    for (int mt = 0; mt < 4; mt++)
#pragma unroll
        for (int nt = 0; nt < 4; nt++)
#pragma unroll
            for (int i = 0; i < 4; i++) acc[mt][nt][i] = 0.f;

    gemm_mainloop_pl(g_Ah, g_Al, g_Woh, g_Wol, bm, bn, smw, acc, wm, wn, lane, tid);

#pragma unroll
    for (int mt = 0; mt < 4; ++mt)
#pragma unroll
        for (int nt = 0; nt < 4; ++nt) {
            const int row  = bm + wm + mt * 16 + lr;
            const int col0 = bn + wn + nt * 8 + lc * 2;
            const float* d = acc[mt][nt];
            *(float2*)(C + (size_t)row * 1024 + col0)       = make_float2(d[0], d[1]);
            *(float2*)(C + (size_t)(row + 8) * 1024 + col0) = make_float2(d[2], d[3]);
        }
}

// ------------------------- flash attention: interleaved mma pairs -------------------------
#define KSTR 36
__global__ __launch_bounds__(128, 4) void flash_attn6(
    const unsigned char* __restrict__ mask)
{
    __shared__ __align__(16) uint32_t SKh[64*KSTR], SKl[64*KSTR], SVh[64*KSTR], SVl[64*KSTR];

    const int tid = threadIdx.x;
    const int w = tid >> 5, lane = tid & 31;
    const int lr = lane >> 2, lc = lane & 3;
    const int bh = blockIdx.y, b = bh >> 4, h = bh & 15;
    const int q0 = blockIdx.x * 64;
    const int t0 = q0 + w * 16;
    const bool anymask = (g_mask_any != 0);

    uint32_t qh[4][4], ql[4][4];
    {
        const uint2* q0p = g_Qpk + ((size_t)bh * 2048 + t0 + lr) * 32;
        const uint2* q1p = q0p + 8 * 32;
#pragma unroll
        for (int c = 0; c < 4; c++) {
            const int j = c * 8 + lc;
            uint2 u;
            u = q0p[j];     qh[c][0] = u.x; ql[c][0] = u.y;
            u = q1p[j];     qh[c][1] = u.x; ql[c][1] = u.y;
            u = q0p[j + 4]; qh[c][2] = u.x; ql[c][2] = u.y;
            u = q1p[j + 4]; qh[c][3] = u.x; ql[c][3] = u.y;
        }
    }

    float m0 = -1e30f, m1 = -1e30f, l0 = 0.f, l1 = 0.f;
    float o[8][4];
#pragma unroll
    for (int nt = 0; nt < 8; nt++)
#pragma unroll
        for (int i = 0; i < 4; i++) o[nt][i] = 0.f;

    const unsigned char* mrow0 = mask + ((size_t)b * 2048 + t0 + lr) * 2048;
    const unsigned char* mrow1 = mrow0 + 8 * 2048;

    const uint32_t skh = s2u(SKh), skl = s2u(SKl), svh = s2u(SVh), svl = s2u(SVl);
    const int lrow = (lane & 7) + ((lane >> 3) & 1) * 8;
    const int lseg = (lane >> 4) * 16;

    for (int kt = 0; kt < 2048; kt += 64) {
        __syncthreads();
        {
            const uint32_t* KH = g_Kh + ((size_t)bh * 2048 + kt) * 32;
            const uint32_t* KL = g_Kl + ((size_t)bh * 2048 + kt) * 32;
            const uint32_t* VH = g_Vh + (size_t)bh * 64 * 1024 + (kt >> 1);
            const uint32_t* VL = g_Vl + (size_t)bh * 64 * 1024 + (kt >> 1);
#pragma unroll
            for (int i = 0; i < 4; i++) {
                int idx = tid + i * 128;
                int r = idx >> 3, j4 = (idx & 7) * 4;
                *(uint4*)&SKh[r * KSTR + j4] = *(const uint4*)&KH[r * 32 + j4];
                *(uint4*)&SKl[r * KSTR + j4] = *(const uint4*)&KL[r * 32 + j4];
                *(uint4*)&SVh[r * KSTR + j4] = *(const uint4*)&VH[(size_t)r * 1024 + j4];
                *(uint4*)&SVl[r * KSTR + j4] = *(const uint4*)&VL[(size_t)r * 1024 + j4];
            }
        }
        __syncthreads();

        // S = Q K^T (term-major within p: dependent mmas 2 apart)
        float s[8][4];
#pragma unroll
        for (int nt = 0; nt < 8; nt++)
#pragma unroll
            for (int i = 0; i < 4; i++) s[nt][i] = 0.f;
#pragma unroll
        for (int c = 0; c < 4; c++) {
#pragma unroll
            for (int p = 0; p < 4; p++) {
                uint32_t kbh[4], kbl[4];
                uint32_t ra = (uint32_t)((p * 16 + lrow) * KSTR) * 4 + c * 32 + lseg;
                ldx4(kbh, skh + ra);
                ldx4(kbl, skl + ra);
                mma_bf16(s[2*p],   qh[c], kbh[0], kbh[2]);
                mma_bf16(s[2*p+1], qh[c], kbh[1], kbh[3]);
                mma_bf16(s[2*p],   qh[c], kbl[0], kbl[2]);
                mma_bf16(s[2*p+1], qh[c], kbl[1], kbl[3]);
                mma_bf16(s[2*p],   ql[c], kbh[0], kbh[2]);
                mma_bf16(s[2*p+1], ql[c], kbh[1], kbh[3]);
            }
        }

        if (anymask) {
#pragma unroll
            for (int nt = 0; nt < 8; nt++) {
                const int cc = kt + nt * 8 + lc * 2;
                if (mrow0[cc])     s[nt][0] = -1e30f;
                if (mrow0[cc + 1]) s[nt][1] = -1e30f;
                if (mrow1[cc])     s[nt][2] = -1e30f;
                if (mrow1[cc + 1]) s[nt][3] = -1e30f;
            }
        }

        float tm0 = -1e30f, tm1 = -1e30f;
#pragma unroll
        for (int nt = 0; nt < 8; nt++) {
            tm0 = fmaxf(tm0, fmaxf(s[nt][0], s[nt][1]));
            tm1 = fmaxf(tm1, fmaxf(s[nt][2], s[nt][3]));
        }
        tm0 = fmaxf(tm0, __shfl_xor_sync(0xffffffff, tm0, 1));
        tm0 = fmaxf(tm0, __shfl_xor_sync(0xffffffff, tm0, 2));
        tm1 = fmaxf(tm1, __shfl_xor_sync(0xffffffff, tm1, 1));
        tm1 = fmaxf(tm1, __shfl_xor_sync(0xffffffff, tm1, 2));
        float mn0 = fmaxf(m0, tm0), mn1 = fmaxf(m1, tm1);
        float cr0 = ex2(m0 - mn0), cr1 = ex2(m1 - mn1);
        m0 = mn0; m1 = mn1;
        float ts0 = 0.f, ts1 = 0.f;
#pragma unroll
        for (int nt = 0; nt < 8; nt++) {
            s[nt][0] = ex2(s[nt][0] - mn0);
            s[nt][1] = ex2(s[nt][1] - mn0);
            s[nt][2] = ex2(s[nt][2] - mn1);
            s[nt][3] = ex2(s[nt][3] - mn1);
            ts0 += s[nt][0] + s[nt][1];
            ts1 += s[nt][2] + s[nt][3];
        }
        ts0 += __shfl_xor_sync(0xffffffff, ts0, 1);
        ts0 += __shfl_xor_sync(0xffffffff, ts0, 2);
        ts1 += __shfl_xor_sync(0xffffffff, ts1, 1);
        ts1 += __shfl_xor_sync(0xffffffff, ts1, 2);
        l0 = l0 * cr0 + ts0;
        l1 = l1 * cr1 + ts1;
#pragma unroll
        for (int nt = 0; nt < 8; nt++) {
            o[nt][0] *= cr0; o[nt][1] *= cr0;
            o[nt][2] *= cr1; o[nt][3] *= cr1;
        }

        // PV (same interleave)
#pragma unroll
        for (int kc = 0; kc < 4; kc++) {
            uint32_t ph[4], pl[4];
            split2(s[2*kc][0],   s[2*kc][1],   ph[0], pl[0]);
            split2(s[2*kc][2],   s[2*kc][3],   ph[1], pl[1]);
            split2(s[2*kc+1][0], s[2*kc+1][1], ph[2], pl[2]);
            split2(s[2*kc+1][2], s[2*kc+1][3], ph[3], pl[3]);
#pragma unroll
            for (int p = 0; p < 4; p++) {
                uint32_t vbh[4], vbl[4];
                uint32_t ra = (uint32_t)((p * 16 + lrow) * KSTR) * 4 + kc * 32 + lseg;
                ldx4(vbh, svh + ra);
                ldx4(vbl, svl + ra);
                mma_bf16(o[2*p],   ph, vbh[0], vbh[2]);
                mma_bf16(o[2*p+1], ph, vbh[1], vbh[3]);
                mma_bf16(o[2*p],   ph, vbl[0], vbl[2]);
                mma_bf16(o[2*p+1], ph, vbl[1], vbl[3]);
                mma_bf16(o[2*p],   pl, vbh[0], vbh[2]);
                mma_bf16(o[2*p+1], pl, vbh[1], vbh[3]);
            }
        }
    }

    const float inv0 = 1.f / l0, inv1 = 1.f / l1;
    uint32_t* A0h = g_Ah + ((size_t)b * 2048 + t0 + lr) * 512 + h * 32;
    uint32_t* A0l = g_Al + ((size_t)b * 2048 + t0 + lr) * 512 + h * 32;
#pragma unroll
    for (int nt = 0; nt < 8; nt++) {
        const int j = nt * 4 + lc;
        uint32_t hh, ll;
        split2(o[nt][0] * inv0, o[nt][1] * inv0, hh, ll);
        A0h[j] = hh; A0l[j] = ll;
        split2(o[nt][2] * inv1, o[nt][3] * inv1, hh, ll);
        A0h[8 * 512 + j] = hh; A0l[8 * 512 + j] = ll;
    }
}

extern "C" void kernel_launch(void* const* d_in, const int* in_sizes, int n_in,
                              void* d_out, int out_size)
{
    const float* query = (const float*)d_in[0];
    const float* key   = (const float*)d_in[1];
    const float* value = (const float*)d_in[2];
    const unsigned char* mask = (const unsigned char*)d_in[3];
    const float* Wq = (const float*)d_in[4];
    const float* Wk = (const float*)d_in[5];
    const float* Wv = (const float*)d_in[6];
    const float* Wo = (const float*)d_in[7];

    const int SMEM_GEMM = 2 * STW * 4;   // 81920 B
    cudaFuncSetAttribute(gemm_qkv,   cudaFuncAttributeMaxDynamicSharedMemorySize, SMEM_GEMM);
    cudaFuncSetAttribute(gemm_oproj, cudaFuncAttributeMaxDynamicSharedMemorySize, SMEM_GEMM);

    zero_flag<<<1, 1>>>();
    mask_scan<<<256, 256>>>((const uint4*)mask, (B_ * T_ * T_) / 16);

    pack_all<<<2048, 256>>>(query, key, value, Wq, Wk, Wv, Wo);

    dim3 gq(24, 32);
    gemm_qkv<<<gq, 256, SMEM_GEMM>>>();

    dim3 gv(32, 32);
    v_pack<<<gv, 128>>>();

    dim3 ga(T_ / 64, B_ * H_);
    flash_attn6<<<ga, 128>>>(mask);

    dim3 go(8, 32);
    gemm_oproj<<<go, 256, SMEM_GEMM>>>((float*)d_out);
}